// round 11
// baseline (speedup 1.0000x reference)
#include <cuda_runtime.h>
#include <cuda_bf16.h>
#include <math.h>
#include <stdint.h>

#define HID   128
#define NODEF 256
#define NBINS 22
#define ETILE 128
#define TW    512
#define WTP   132

// ---- smem byte offsets ----
#define OFF_W2HI 0
#define OFF_W2LO 32768
#define OFF_W3HI 65536
#define OFF_W3LO 98304
#define OFF_AHI  131072
#define OFF_ALO  163840
#define OFF_WT   196608                  // float[46][WTP], rows 44/45 zero
#define OFF_SA   (OFF_WT + 46*WTP*4)     // 220896
#define OFF_SB2  (OFF_SA + 512)
#define OFF_SB3  (OFF_SB2 + 512)
#define OFF_SG   (OFF_SB3 + 512)
#define OFF_SBT  (OFF_SG + 512)
#define OFF_MSK  (OFF_SBT + 512)
#define OFF_BIN1 (OFF_MSK + 512)
#define OFF_BIN2 (OFF_BIN1 + 512)
#define OFF_RSUM (OFF_BIN2 + 512)        // float[4][128]
#define OFF_RSQ  (OFF_RSUM + 2048)       // float[4][128]
#define SMEM_BYTES (OFF_RSQ + 2048)      // 229088

__device__ float g_A[512 * HID];
__device__ float g_B[512 * HID];
__device__ float g_R[1023 * HID];

// ---- helpers ----
__device__ __forceinline__ uint32_t pk2(float a, float b) {  // lo = a, hi = b
    uint32_t r;
    asm("cvt.rn.bf16x2.f32 %0, %1, %2;" : "=r"(r) : "f"(b), "f"(a));
    return r;
}
__device__ __forceinline__ float2 up2(uint32_t p) {
    float2 r;
    asm("{ .reg .b16 l,h; mov.b32 {l,h}, %2; cvt.f32.bf16 %0, l; cvt.f32.bf16 %1, h; }"
        : "=f"(r.x), "=f"(r.y) : "r"(p));
    return r;
}
__device__ __forceinline__ void mma16816(float (&d)[4], const uint4& a, uint32_t b0, uint32_t b1) {
    asm volatile("mma.sync.aligned.m16n8k16.row.col.f32.bf16.bf16.f32 "
                 "{%0,%1,%2,%3}, {%4,%5,%6,%7}, {%8,%9}, {%0,%1,%2,%3};"
                 : "+f"(d[0]), "+f"(d[1]), "+f"(d[2]), "+f"(d[3])
                 : "r"(a.x), "r"(a.y), "r"(a.z), "r"(a.w), "r"(b0), "r"(b1));
}

// ---- merged precompute: blocks [0,N) -> A/B rows; [N, 3N-1) -> R rows ----
__global__ void k_pre2(const float* __restrict__ nf, const float* __restrict__ Wn,
                       const float* __restrict__ bn, const float* __restrict__ W1,
                       const float* __restrict__ b1, const float* __restrict__ flow,
                       const float* __restrict__ Wrp, const float* __restrict__ brp,
                       int N) {
    const int c = threadIdx.x;
    if ((int)blockIdx.x < N) {
        __shared__ float row[NODEF];
        __shared__ float n2e[HID];
        const int i = blockIdx.x;
        row[c] = nf[i * NODEF + c];
        row[c + 128] = nf[i * NODEF + 128 + c];
        __syncthreads();
        float acc = bn[c];
#pragma unroll 8
        for (int k = 0; k < NODEF; k++) acc += row[k] * Wn[k * HID + c];
        n2e[c] = acc;
        __syncthreads();
        const float fi = flow[i];
        float a = b1[c] + fi * W1[428 * HID + c];
        float bb = fi * W1[429 * HID + c];
#pragma unroll 8
        for (int k = 0; k < HID; k++) {
            float v = n2e[k];
            a += v * W1[k * HID + c];
            bb += v * W1[(128 + k) * HID + c];
        }
        g_A[i * HID + c] = a;
        g_B[i * HID + c] = bb;
    } else {
        __shared__ float emb[HID];
        __shared__ float rp[HID];
        const int bi = blockIdx.x - N;           // 0 .. 2N-2
        const float d = (float)(bi - (N - 1));
        if (c < 64) {
            float den = (float)pow(2056.0, (double)c * (1.0 / 64.0));
            float ang = (d * 3.14159274101257324f) / den;
            emb[c] = (float)sin((double)ang);
            emb[c + 64] = (float)cos((double)ang);
        }
        __syncthreads();
        float acc = brp[c];
#pragma unroll 8
        for (int k = 0; k < HID; k++) acc += emb[k] * Wrp[k * HID + c];
        rp[c] = acc;
        __syncthreads();
        float r = 0.0f;
#pragma unroll 8
        for (int k = 0; k < HID; k++) r += rp[k] * W1[(256 + k) * HID + c];
        g_R[bi * HID + c] = r;
    }
}

__device__ __forceinline__ int calc_bin(const float* __restrict__ p, int i, int j) {
    const float dx = __ldg(&p[3 * i + 0]) - __ldg(&p[3 * j + 0]);
    const float dy = __ldg(&p[3 * i + 1]) - __ldg(&p[3 * j + 1]);
    const float dz = __ldg(&p[3 * i + 2]) - __ldg(&p[3 * j + 2]);
    const float d = sqrtf((dx * dx + dy * dy) + dz * dz);
    const float step = (20.0f - 0.001f) / 21.0f;
    int bin = -1;
#pragma unroll
    for (int k = 0; k < NBINS; k++) {
        const float lo = 0.001f + (float)k * step;
        const float hi = (k == NBINS - 1) ? 1e8f : (0.001f + (float)(k + 1) * step);
        if (d > lo && d < hi) bin = k;
    }
    return bin;
}

// one layer: warp tile 32 edges (mt0,mt1) x 32 channels (nt pairs pr_g = 2wn, 2wn+1)
__device__ __forceinline__ void gemm_mma(const char* smc, int woff_hi, int woff_lo,
                                         int wm, int wn, int lane, float (&acc)[2][4][4]) {
#pragma unroll
    for (int m = 0; m < 2; m++)
#pragma unroll
        for (int nt = 0; nt < 4; nt++)
#pragma unroll
            for (int q = 0; q < 4; q++) acc[m][nt][q] = 0.0f;
    const int mt0 = 2 * wm, mt1 = 2 * wm + 1;
#pragma unroll 2
    for (int ks = 0; ks < 8; ks++) {
        const uint4 ah0 = *(const uint4*)(smc + OFF_AHI + ((mt0 * 8 + ks) * 32 + lane) * 16);
        const uint4 al0 = *(const uint4*)(smc + OFF_ALO + ((mt0 * 8 + ks) * 32 + lane) * 16);
        const uint4 ah1 = *(const uint4*)(smc + OFF_AHI + ((mt1 * 8 + ks) * 32 + lane) * 16);
        const uint4 al1 = *(const uint4*)(smc + OFF_ALO + ((mt1 * 8 + ks) * 32 + lane) * 16);
#pragma unroll
        for (int pr = 0; pr < 2; pr++) {
            const int prg = wn * 2 + pr;
            const uint4 bh = *(const uint4*)(smc + woff_hi + ((ks * 8 + prg) * 32 + lane) * 16);
            const uint4 bl = *(const uint4*)(smc + woff_lo + ((ks * 8 + prg) * 32 + lane) * 16);
            // even nt (sub 0): bh.x,bh.y ; odd nt (sub 1): bh.z,bh.w
            mma16816(acc[0][2 * pr + 0], ah0, bh.x, bh.y);
            mma16816(acc[0][2 * pr + 0], ah0, bl.x, bl.y);
            mma16816(acc[0][2 * pr + 0], al0, bh.x, bh.y);
            mma16816(acc[1][2 * pr + 0], ah1, bh.x, bh.y);
            mma16816(acc[1][2 * pr + 0], ah1, bl.x, bl.y);
            mma16816(acc[1][2 * pr + 0], al1, bh.x, bh.y);
            mma16816(acc[0][2 * pr + 1], ah0, bh.z, bh.w);
            mma16816(acc[0][2 * pr + 1], ah0, bl.z, bl.w);
            mma16816(acc[0][2 * pr + 1], al0, bh.z, bh.w);
            mma16816(acc[1][2 * pr + 1], ah1, bh.z, bh.w);
            mma16816(acc[1][2 * pr + 1], ah1, bl.z, bl.w);
            mma16816(acc[1][2 * pr + 1], al1, bh.z, bh.w);
        }
    }
}

// ---- main persistent kernel ----
__global__ void __launch_bounds__(TW, 1) k_main(
    const float* __restrict__ trans, const float* __restrict__ sctrans,
    const float* __restrict__ emask, const float* __restrict__ W1,
    const float* __restrict__ W2, const float* __restrict__ b2,
    const float* __restrict__ W3, const float* __restrict__ b3,
    const float* __restrict__ lng, const float* __restrict__ lnb,
    float* __restrict__ out, int N) {
    extern __shared__ char smc[];
    float* sWT  = (float*)(smc + OFF_WT);
    float* sA   = (float*)(smc + OFF_SA);
    float* smk  = (float*)(smc + OFF_MSK);
    int* sbin1  = (int*)(smc + OFF_BIN1);
    int* sbin2  = (int*)(smc + OFF_BIN2);
    float* rsum = (float*)(smc + OFF_RSUM);
    float* rsq  = (float*)(smc + OFF_RSQ);

    const int tid = threadIdx.x, lane = tid & 31, wid = tid >> 5;
    const int wm = wid & 3, wn = wid >> 2;      // 4x4 warp grid: 32e x 32c tiles
    const int gq = lane >> 2, tq = lane & 3;

    // one-time: W2/W3 -> bf16 hi/lo B-fragment layout (nt-paired); W1 tail; vectors
    for (int idx = tid; idx < 64 * HID; idx += TW) {   // 8192 k-pair words
        const int n = idx >> 6, k = (idx & 63) * 2;
        const int ntg = n >> 3, gg = n & 7;
        const int t = (k >> 1) & 3, ks = k >> 4, r = (k >> 3) & 1;
        const int woff = ((ks * 8 + (ntg >> 1)) * 32 + 4 * gg + t) * 16 + (ntg & 1) * 8 + r * 4;
        {
            const float w0 = W2[k * HID + n], w1 = W2[(k + 1) * HID + n];
            const uint32_t hi = pk2(w0, w1);
            const float2 f = up2(hi);
            *(uint32_t*)(smc + OFF_W2HI + woff) = hi;
            *(uint32_t*)(smc + OFF_W2LO + woff) = pk2(w0 - f.x, w1 - f.y);
        }
        {
            const float w0 = W3[k * HID + n], w1 = W3[(k + 1) * HID + n];
            const uint32_t hi = pk2(w0, w1);
            const float2 f = up2(hi);
            *(uint32_t*)(smc + OFF_W3HI + woff) = hi;
            *(uint32_t*)(smc + OFF_W3LO + woff) = pk2(w0 - f.x, w1 - f.y);
        }
    }
    for (int idx = tid; idx < 46 * HID; idx += TW) {
        const int q = idx >> 7, c = idx & 127;
        sWT[q * WTP + c] = (q < 44) ? W1[(384 + q) * HID + c] : 0.0f;
    }
    if (tid < HID) {
        ((float*)(smc + OFF_SB2))[tid] = b2[tid];
        ((float*)(smc + OFF_SB3))[tid] = b3[tid];
        ((float*)(smc + OFF_SG))[tid]  = lng[tid];
        ((float*)(smc + OFF_SBT))[tid] = lnb[tid];
    }
    __syncthreads();

    const int tpr = N / ETILE, ntiles = N * tpr;

    for (int t0 = blockIdx.x; t0 < ntiles; t0 += gridDim.x) {
        const int i = t0 / tpr;
        const int jb = (t0 - i * tpr) * ETILE;

        if (tid < ETILE) {
            const int j = jb + tid;
            const int q1 = calc_bin(trans, i, j);
            const int q2 = calc_bin(sctrans, i, j);
            sbin1[tid] = (q1 < 0 ? 44 : q1) * WTP;
            sbin2[tid] = (q2 < 0 ? 44 : 22 + q2) * WTP;
            smk[tid] = emask[i * N + j];
        } else if (tid < 2 * ETILE) {
            sA[tid - 128] = g_A[i * HID + (tid - 128)];
        }
        __syncthreads();

        // ---- phase 0: assemble h1 (4 threads/edge, 32 ch each), split, A-frag store ----
        {
            const int e = tid >> 2, chb = (tid & 3) * 32;
            const int mt = e >> 4, g8 = e & 7, rowhi = (e >> 3) & 1;
            const int j = jb + e;
            const float* bp = &g_B[j * HID];
            const float* rp = &g_R[(size_t)(i - j + N - 1) * HID];
            const float* t1p = &sWT[sbin1[e]];
            const float* t2p = &sWT[sbin2[e]];
#pragma unroll
            for (int cg = 0; cg < 4; cg++) {
                const int c0 = chb + cg * 8;
                float v[8];
#pragma unroll
                for (int h4 = 0; h4 < 2; h4++) {
                    const int c = c0 + 4 * h4;
                    const float4 av = *(const float4*)&sA[c];
                    const float4 bv = *(const float4*)&bp[c];
                    const float4 rv = *(const float4*)&rp[c];
                    const float4 w1v = *(const float4*)&t1p[c];
                    const float4 w2v = *(const float4*)&t2p[c];
                    v[4 * h4 + 0] = fmaxf(av.x + bv.x + rv.x + w1v.x + w2v.x, 0.0f);
                    v[4 * h4 + 1] = fmaxf(av.y + bv.y + rv.y + w1v.y + w2v.y, 0.0f);
                    v[4 * h4 + 2] = fmaxf(av.z + bv.z + rv.z + w1v.z + w2v.z, 0.0f);
                    v[4 * h4 + 3] = fmaxf(av.w + bv.w + rv.w + w1v.w + w2v.w, 0.0f);
                }
                const int ks = c0 >> 4, khalf = (c0 >> 3) & 1;
                const int r = khalf * 2 + rowhi;
                const int base = ((mt * 8 + ks) * 32 + 4 * g8) * 16 + r * 4;
#pragma unroll
                for (int tt = 0; tt < 4; tt++) {
                    const uint32_t hi = pk2(v[2 * tt], v[2 * tt + 1]);
                    const float2 f = up2(hi);
                    *(uint32_t*)(smc + OFF_AHI + base + tt * 16) = hi;
                    *(uint32_t*)(smc + OFF_ALO + base + tt * 16) =
                        pk2(v[2 * tt] - f.x, v[2 * tt + 1] - f.y);
                }
            }
        }
        __syncthreads();

        float acc[2][4][4];

        // ---- layer 2 GEMM + epilogue (bias+relu+resplit into A tiles) ----
        gemm_mma(smc, OFF_W2HI, OFF_W2LO, wm, wn, lane, acc);
        __syncthreads();   // all A reads done before overwrite
#pragma unroll
        for (int m = 0; m < 2; m++) {
            const int mtg = 2 * wm + m;
#pragma unroll
            for (int nt = 0; nt < 4; nt++) {
                const int ntg = wn * 4 + nt;
                const int col = ntg * 8 + 2 * tq;
                const float2 bb = *(const float2*)(smc + OFF_SB2 + col * 4);
                const float v0 = fmaxf(acc[m][nt][0] + bb.x, 0.0f);
                const float v1 = fmaxf(acc[m][nt][1] + bb.y, 0.0f);
                const float v2 = fmaxf(acc[m][nt][2] + bb.x, 0.0f);
                const float v3 = fmaxf(acc[m][nt][3] + bb.y, 0.0f);
                const uint32_t hi0 = pk2(v0, v1);
                const float2 f0 = up2(hi0);
                const uint32_t lo0 = pk2(v0 - f0.x, v1 - f0.y);
                const uint32_t hi1 = pk2(v2, v3);
                const float2 f1 = up2(hi1);
                const uint32_t lo1 = pk2(v2 - f1.x, v3 - f1.y);
                const int ks = ntg >> 1, roff = (ntg & 1) * 2;
                const int boff = (((mtg * 8 + ks) * 32 + lane) * 4 + roff) * 4;
                *(uint2*)(smc + OFF_AHI + boff) = make_uint2(hi0, hi1);
                *(uint2*)(smc + OFF_ALO + boff) = make_uint2(lo0, lo1);
            }
        }
        __syncthreads();

        // ---- layer 3 GEMM ----
        gemm_mma(smc, OFF_W3HI, OFF_W3LO, wm, wn, lane, acc);

        // ---- bias + LayerNorm + mask + store ----
        {
            float s[2][2] = {{0, 0}, {0, 0}}, q[2][2] = {{0, 0}, {0, 0}};
#pragma unroll
            for (int m = 0; m < 2; m++)
#pragma unroll
                for (int nt = 0; nt < 4; nt++) {
                    const int col = (wn * 4 + nt) * 8 + 2 * tq;
                    const float2 bb = *(const float2*)(smc + OFF_SB3 + col * 4);
                    acc[m][nt][0] += bb.x;
                    acc[m][nt][1] += bb.y;
                    acc[m][nt][2] += bb.x;
                    acc[m][nt][3] += bb.y;
                    s[m][0] += acc[m][nt][0] + acc[m][nt][1];
                    s[m][1] += acc[m][nt][2] + acc[m][nt][3];
                    q[m][0] += acc[m][nt][0] * acc[m][nt][0] + acc[m][nt][1] * acc[m][nt][1];
                    q[m][1] += acc[m][nt][2] * acc[m][nt][2] + acc[m][nt][3] * acc[m][nt][3];
                }
#pragma unroll
            for (int m = 0; m < 2; m++)
#pragma unroll
                for (int h = 0; h < 2; h++) {
                    s[m][h] += __shfl_xor_sync(0xffffffffu, s[m][h], 1);
                    s[m][h] += __shfl_xor_sync(0xffffffffu, s[m][h], 2);
                    q[m][h] += __shfl_xor_sync(0xffffffffu, q[m][h], 1);
                    q[m][h] += __shfl_xor_sync(0xffffffffu, q[m][h], 2);
                }
            if (tq == 0) {
#pragma unroll
                for (int m = 0; m < 2; m++)
#pragma unroll
                    for (int h = 0; h < 2; h++) {
                        const int row = (2 * wm + m) * 16 + gq + 8 * h;
                        rsum[wn * 128 + row] = s[m][h];
                        rsq[wn * 128 + row] = q[m][h];
                    }
            }
            __syncthreads();
#pragma unroll
            for (int m = 0; m < 2; m++)
#pragma unroll
                for (int h = 0; h < 2; h++) {
                    const int row = (2 * wm + m) * 16 + gq + 8 * h;
                    const float S = (rsum[row] + rsum[128 + row]) + (rsum[256 + row] + rsum[384 + row]);
                    const float Q = (rsq[row] + rsq[128 + row]) + (rsq[256 + row] + rsq[384 + row]);
                    const float mu = S * (1.0f / 128.0f);
                    const float var = Q * (1.0f / 128.0f) - mu * mu;
                    const float rstd = rsqrtf(var + 1e-5f);
                    const float msk = smk[row];
                    float* op = &out[((size_t)(i * N + jb + row)) * HID];
#pragma unroll
                    for (int nt = 0; nt < 4; nt++) {
                        const int col = (wn * 4 + nt) * 8 + 2 * tq;
                        const float2 gg = *(const float2*)(smc + OFF_SG + col * 4);
                        const float2 bt = *(const float2*)(smc + OFF_SBT + col * 4);
                        const float a = acc[m][nt][2 * h + 0];
                        const float b = acc[m][nt][2 * h + 1];
                        float2 o;
                        o.x = ((a - mu) * rstd * gg.x + bt.x) * msk;
                        o.y = ((b - mu) * rstd * gg.y + bt.y) * msk;
                        *(float2*)(op + col) = o;
                    }
                }
        }
        __syncthreads();   // A tiles / bins / red reused next iteration
    }
}

// ---- launch ----
extern "C" void kernel_launch(void* const* d_in, const int* in_sizes, int n_in,
                              void* d_out, int out_size) {
    const float* nf    = (const float*)d_in[0];
    const float* trans = (const float*)d_in[1];
    const float* sct   = (const float*)d_in[2];
    const float* emask = (const float*)d_in[3];
    const float* flow  = (const float*)d_in[4];
    const float* W_n2e = (const float*)d_in[5];
    const float* b_n2e = (const float*)d_in[6];
    const float* W_rp  = (const float*)d_in[7];
    const float* b_rp  = (const float*)d_in[8];
    const float* W1    = (const float*)d_in[9];
    const float* b1    = (const float*)d_in[10];
    const float* W2    = (const float*)d_in[11];
    const float* b2    = (const float*)d_in[12];
    const float* W3    = (const float*)d_in[13];
    const float* b3    = (const float*)d_in[14];
    const float* lng   = (const float*)d_in[15];
    const float* lnb   = (const float*)d_in[16];
    float* out = (float*)d_out;

    const int N = in_sizes[4];

    k_pre2<<<3 * N - 1, 128>>>(nf, W_n2e, b_n2e, W1, b1, flow, W_rp, b_rp, N);

    cudaFuncSetAttribute((const void*)k_main,
                         cudaFuncAttributeMaxDynamicSharedMemorySize, SMEM_BYTES);
    k_main<<<152, TW, SMEM_BYTES>>>(trans, sct, emask, W1, W2, b2, W3, b3,
                                    lng, lnb, out, N);
}

// round 12
// speedup vs baseline: 1.2088x; 1.2088x over previous
#include <cuda_runtime.h>
#include <cuda_bf16.h>
#include <math.h>
#include <stdint.h>

#define HID   128
#define NODEF 256
#define NBINS 22
#define ETILE 128
#define TW    512
#define WTP   132
#define HPIT  272            // bytes per h row (256 data + 16 pad), 68 words = 4 mod 32
#define HLO_D 34816          // HLO - HHI

// ---- smem byte offsets ----
#define OFF_W2HI 0
#define OFF_W2LO 32768
#define OFF_W3HI 65536
#define OFF_W3LO 98304
#define OFF_HHI  131072      // 128*272 = 34816
#define OFF_HLO  165888
#define OFF_WT   200704      // float[45][WTP] (row 44 = zeros) = 23760
#define OFF_SB2  224464
#define OFF_SB3  224976
#define OFF_SG   225488
#define OFF_SBT  226000
#define OFF_MSK  226512
#define OFF_BIN1 227024
#define OFF_BIN2 227536
#define OFF_RSUM 228048      // float[4][128]
#define OFF_RSQ  230096      // float[4][128]
#define SMEM_BYTES 232144

__device__ float g_A[512 * HID];
__device__ float g_B[512 * HID];
__device__ float g_R[1023 * HID];

// ---- helpers ----
__device__ __forceinline__ uint32_t pk2(float a, float b) {  // lo = a, hi = b
    uint32_t r;
    asm("cvt.rn.bf16x2.f32 %0, %1, %2;" : "=r"(r) : "f"(b), "f"(a));
    return r;
}
__device__ __forceinline__ float2 up2(uint32_t p) {
    float2 r;
    asm("{ .reg .b16 l,h; mov.b32 {l,h}, %2; cvt.f32.bf16 %0, l; cvt.f32.bf16 %1, h; }"
        : "=f"(r.x), "=f"(r.y) : "r"(p));
    return r;
}
__device__ __forceinline__ void mma16816(float (&d)[4], const uint4& a, uint32_t b0, uint32_t b1) {
    asm volatile("mma.sync.aligned.m16n8k16.row.col.f32.bf16.bf16.f32 "
                 "{%0,%1,%2,%3}, {%4,%5,%6,%7}, {%8,%9}, {%0,%1,%2,%3};"
                 : "+f"(d[0]), "+f"(d[1]), "+f"(d[2]), "+f"(d[3])
                 : "r"(a.x), "r"(a.y), "r"(a.z), "r"(a.w), "r"(b0), "r"(b1));
}
__device__ __forceinline__ uint4 ldmat4(uint32_t a) {
    uint4 r;
    asm volatile("ldmatrix.sync.aligned.m8n8.x4.shared.b16 {%0,%1,%2,%3}, [%4];"
                 : "=r"(r.x), "=r"(r.y), "=r"(r.z), "=r"(r.w) : "r"(a));
    return r;
}
__device__ __forceinline__ void stmat2(uint32_t a, uint32_t r0, uint32_t r1) {
    asm volatile("stmatrix.sync.aligned.m8n8.x2.shared.b16 [%0], {%1,%2};"
                 :: "r"(a), "r"(r0), "r"(r1));
}
__device__ __forceinline__ uint32_t smem_u32(const void* p) {
    uint32_t a;
    asm("{ .reg .u64 t; cvta.to.shared.u64 t, %1; cvt.u32.u64 %0, t; }" : "=r"(a) : "l"(p));
    return a;
}

// ---- merged precompute: blocks [0,N) -> A/B rows; [N, 3N-1) -> R rows ----
__global__ void k_pre2(const float* __restrict__ nf, const float* __restrict__ Wn,
                       const float* __restrict__ bn, const float* __restrict__ W1,
                       const float* __restrict__ b1, const float* __restrict__ flow,
                       const float* __restrict__ Wrp, const float* __restrict__ brp,
                       int N) {
    const int c = threadIdx.x;
    if ((int)blockIdx.x < N) {
        __shared__ float row[NODEF];
        __shared__ float n2e[HID];
        const int i = blockIdx.x;
        row[c] = nf[i * NODEF + c];
        row[c + 128] = nf[i * NODEF + 128 + c];
        __syncthreads();
        float acc = bn[c];
#pragma unroll 8
        for (int k = 0; k < NODEF; k++) acc += row[k] * Wn[k * HID + c];
        n2e[c] = acc;
        __syncthreads();
        const float fi = flow[i];
        float a = b1[c] + fi * W1[428 * HID + c];
        float bb = fi * W1[429 * HID + c];
#pragma unroll 8
        for (int k = 0; k < HID; k++) {
            float v = n2e[k];
            a += v * W1[k * HID + c];
            bb += v * W1[(128 + k) * HID + c];
        }
        g_A[i * HID + c] = a;
        g_B[i * HID + c] = bb;
    } else {
        __shared__ float emb[HID];
        __shared__ float rp[HID];
        const int bi = blockIdx.x - N;
        const float d = (float)(bi - (N - 1));
        if (c < 64) {
            float den = (float)pow(2056.0, (double)c * (1.0 / 64.0));
            float ang = (d * 3.14159274101257324f) / den;
            emb[c] = (float)sin((double)ang);
            emb[c + 64] = (float)cos((double)ang);
        }
        __syncthreads();
        float acc = brp[c];
#pragma unroll 8
        for (int k = 0; k < HID; k++) acc += emb[k] * Wrp[k * HID + c];
        rp[c] = acc;
        __syncthreads();
        float r = 0.0f;
#pragma unroll 8
        for (int k = 0; k < HID; k++) r += rp[k] * W1[(256 + k) * HID + c];
        g_R[bi * HID + c] = r;
    }
}

__device__ __forceinline__ int calc_bin(const float* __restrict__ p, int i, int j) {
    const float dx = __ldg(&p[3 * i + 0]) - __ldg(&p[3 * j + 0]);
    const float dy = __ldg(&p[3 * i + 1]) - __ldg(&p[3 * j + 1]);
    const float dz = __ldg(&p[3 * i + 2]) - __ldg(&p[3 * j + 2]);
    const float d = sqrtf((dx * dx + dy * dy) + dz * dz);
    const float step = (20.0f - 0.001f) / 21.0f;
    int bin = -1;
#pragma unroll
    for (int k = 0; k < NBINS; k++) {
        const float lo = 0.001f + (float)k * step;
        const float hi = (k == NBINS - 1) ? 1e8f : (0.001f + (float)(k + 1) * step);
        if (d > lo && d < hi) bin = k;
    }
    return bin;
}

// one layer: warp tile 32 edges x 32 channels; A via ldmatrix from edge-major h buffers
__device__ __forceinline__ void gemm_mma(const char* smc, uint32_t hhi, int woff_hi, int woff_lo,
                                         int wm, int wn, int lane, uint32_t lmoff,
                                         float (&acc)[2][4][4]) {
#pragma unroll
    for (int m = 0; m < 2; m++)
#pragma unroll
        for (int nt = 0; nt < 4; nt++)
#pragma unroll
            for (int q = 0; q < 4; q++) acc[m][nt][q] = 0.0f;
    const uint32_t a0b = hhi + (2 * wm) * 16 * HPIT + lmoff;
#pragma unroll 2
    for (int ks = 0; ks < 8; ks++) {
        const uint32_t ar = a0b + ks * 32;
        const uint4 ah0 = ldmat4(ar);
        const uint4 al0 = ldmat4(ar + HLO_D);
        const uint4 ah1 = ldmat4(ar + 16 * HPIT);
        const uint4 al1 = ldmat4(ar + 16 * HPIT + HLO_D);
#pragma unroll
        for (int pr = 0; pr < 2; pr++) {
            const int prg = wn * 2 + pr;
            const uint4 bh = *(const uint4*)(smc + woff_hi + ((ks * 8 + prg) * 32 + lane) * 16);
            const uint4 bl = *(const uint4*)(smc + woff_lo + ((ks * 8 + prg) * 32 + lane) * 16);
            mma16816(acc[0][2 * pr + 0], ah0, bh.x, bh.y);
            mma16816(acc[0][2 * pr + 0], ah0, bl.x, bl.y);
            mma16816(acc[0][2 * pr + 0], al0, bh.x, bh.y);
            mma16816(acc[1][2 * pr + 0], ah1, bh.x, bh.y);
            mma16816(acc[1][2 * pr + 0], ah1, bl.x, bl.y);
            mma16816(acc[1][2 * pr + 0], al1, bh.x, bh.y);
            mma16816(acc[0][2 * pr + 1], ah0, bh.z, bh.w);
            mma16816(acc[0][2 * pr + 1], ah0, bl.z, bl.w);
            mma16816(acc[0][2 * pr + 1], al0, bh.z, bh.w);
            mma16816(acc[1][2 * pr + 1], ah1, bh.z, bh.w);
            mma16816(acc[1][2 * pr + 1], ah1, bl.z, bl.w);
            mma16816(acc[1][2 * pr + 1], al1, bh.z, bh.w);
        }
    }
}

// ---- main persistent kernel ----
__global__ void __launch_bounds__(TW, 1) k_main(
    const float* __restrict__ trans, const float* __restrict__ sctrans,
    const float* __restrict__ emask, const float* __restrict__ W1,
    const float* __restrict__ W2, const float* __restrict__ b2,
    const float* __restrict__ W3, const float* __restrict__ b3,
    const float* __restrict__ lng, const float* __restrict__ lnb,
    float* __restrict__ out, int N) {
    extern __shared__ char smc[];
    float* sWT  = (float*)(smc + OFF_WT);
    float* smk  = (float*)(smc + OFF_MSK);
    int* sbin1  = (int*)(smc + OFF_BIN1);
    int* sbin2  = (int*)(smc + OFF_BIN2);
    float* rsum = (float*)(smc + OFF_RSUM);
    float* rsq  = (float*)(smc + OFF_RSQ);

    const int tid = threadIdx.x, lane = tid & 31, wid = tid >> 5;
    const int wm = wid & 3, wn = wid >> 2;
    const int gq = lane >> 2, tq = lane & 3;
    const uint32_t smb = smem_u32(smc);
    const uint32_t hhi = smb + OFF_HHI;
    // ldmatrix per-lane offset: rows (lane&7)+8*((lane>>3)&1), k-half (lane>>4)
    const uint32_t lmoff = (uint32_t)(((lane & 7) + 8 * ((lane >> 3) & 1)) * HPIT + (lane >> 4) * 16);
    // stmatrix per-lane offset: rows (lane&7)+8*((lane>>3)&1)
    const uint32_t smoff = (uint32_t)(((lane & 7) + 8 * ((lane >> 3) & 1)) * HPIT);

    // one-time: W2/W3 -> bf16 hi/lo B-fragment layout (nt-paired); W1 tail; vectors
    for (int idx = tid; idx < 64 * HID; idx += TW) {
        const int n = idx >> 6, k = (idx & 63) * 2;
        const int ntg = n >> 3, gg = n & 7;
        const int t = (k >> 1) & 3, ks = k >> 4, r = (k >> 3) & 1;
        const int woff = ((ks * 8 + (ntg >> 1)) * 32 + 4 * gg + t) * 16 + (ntg & 1) * 8 + r * 4;
        {
            const float w0 = W2[k * HID + n], w1 = W2[(k + 1) * HID + n];
            const uint32_t hi = pk2(w0, w1);
            const float2 f = up2(hi);
            *(uint32_t*)(smc + OFF_W2HI + woff) = hi;
            *(uint32_t*)(smc + OFF_W2LO + woff) = pk2(w0 - f.x, w1 - f.y);
        }
        {
            const float w0 = W3[k * HID + n], w1 = W3[(k + 1) * HID + n];
            const uint32_t hi = pk2(w0, w1);
            const float2 f = up2(hi);
            *(uint32_t*)(smc + OFF_W3HI + woff) = hi;
            *(uint32_t*)(smc + OFF_W3LO + woff) = pk2(w0 - f.x, w1 - f.y);
        }
    }
    for (int idx = tid; idx < 45 * HID; idx += TW) {
        const int q = idx >> 7, c = idx & 127;
        sWT[q * WTP + c] = (q < 44) ? W1[(384 + q) * HID + c] : 0.0f;
    }
    if (tid < HID) {
        ((float*)(smc + OFF_SB2))[tid] = b2[tid];
        ((float*)(smc + OFF_SB3))[tid] = b3[tid];
        ((float*)(smc + OFF_SG))[tid]  = lng[tid];
        ((float*)(smc + OFF_SBT))[tid] = lnb[tid];
    }
    __syncthreads();

    const int tpr = N / ETILE, ntiles = N * tpr;

    for (int t0 = blockIdx.x; t0 < ntiles; t0 += gridDim.x) {
        const int i = t0 / tpr;
        const int jb = (t0 - i * tpr) * ETILE;

        if (tid < ETILE) {
            const int j = jb + tid;
            const int q1 = calc_bin(trans, i, j);
            const int q2 = calc_bin(sctrans, i, j);
            sbin1[tid] = (q1 < 0 ? 44 : q1) * WTP;
            sbin2[tid] = (q2 < 0 ? 44 : 22 + q2) * WTP;
            smk[tid] = emask[i * N + j];
        }
        __syncthreads();

        // ---- phase 0: assemble h1, split hi/lo, edge-major STS.128 (conflict-free) ----
        {
            const int e = 8 * wid + (lane & 7);     // lanes 0-7 -> 8 distinct rows
            const int sub = lane >> 3;              // 0..3 -> 32-channel block
            const int j = jb + e;
            const float* ap = &g_A[i * HID];
            const float* bp = &g_B[j * HID];
            const float* rp = &g_R[(size_t)(i - j + N - 1) * HID];
            const float* t1p = &sWT[sbin1[e]];
            const float* t2p = &sWT[sbin2[e]];
#pragma unroll
            for (int cg = 0; cg < 4; cg++) {
                const int c0 = sub * 32 + cg * 8;
                float v[8];
#pragma unroll
                for (int h4 = 0; h4 < 2; h4++) {
                    const int c = c0 + 4 * h4;
                    const float4 av = *(const float4*)&ap[c];
                    const float4 bv = *(const float4*)&bp[c];
                    const float4 rv = *(const float4*)&rp[c];
                    const float4 w1v = *(const float4*)&t1p[c];
                    const float4 w2v = *(const float4*)&t2p[c];
                    v[4 * h4 + 0] = fmaxf(av.x + bv.x + rv.x + w1v.x + w2v.x, 0.0f);
                    v[4 * h4 + 1] = fmaxf(av.y + bv.y + rv.y + w1v.y + w2v.y, 0.0f);
                    v[4 * h4 + 2] = fmaxf(av.z + bv.z + rv.z + w1v.z + w2v.z, 0.0f);
                    v[4 * h4 + 3] = fmaxf(av.w + bv.w + rv.w + w1v.w + w2v.w, 0.0f);
                }
                uint32_t hw[4], lw[4];
#pragma unroll
                for (int q = 0; q < 4; q++) {
                    const uint32_t hi = pk2(v[2 * q], v[2 * q + 1]);
                    const float2 f = up2(hi);
                    hw[q] = hi;
                    lw[q] = pk2(v[2 * q] - f.x, v[2 * q + 1] - f.y);
                }
                const int hb = e * HPIT + c0 * 2;
                *(uint4*)(smc + OFF_HHI + hb) = make_uint4(hw[0], hw[1], hw[2], hw[3]);
                *(uint4*)(smc + OFF_HLO + hb) = make_uint4(lw[0], lw[1], lw[2], lw[3]);
            }
        }
        __syncthreads();

        float acc[2][4][4];

        // ---- layer 2 GEMM + epilogue (bias+relu+resplit via stmatrix) ----
        gemm_mma(smc, hhi, OFF_W2HI, OFF_W2LO, wm, wn, lane, lmoff, acc);
        __syncthreads();   // all h1 reads done before overwrite
#pragma unroll
        for (int m = 0; m < 2; m++) {
            const uint32_t rowb = hhi + (uint32_t)((2 * wm + m) * 16 * HPIT) + smoff;
#pragma unroll
            for (int nt = 0; nt < 4; nt++) {
                const int ntg = wn * 4 + nt;
                const int col = ntg * 8 + 2 * tq;
                const float2 bb = *(const float2*)(smc + OFF_SB2 + col * 4);
                const float v0 = fmaxf(acc[m][nt][0] + bb.x, 0.0f);
                const float v1 = fmaxf(acc[m][nt][1] + bb.y, 0.0f);
                const float v2 = fmaxf(acc[m][nt][2] + bb.x, 0.0f);
                const float v3 = fmaxf(acc[m][nt][3] + bb.y, 0.0f);
                const uint32_t hi0 = pk2(v0, v1);
                const float2 f0 = up2(hi0);
                const uint32_t lo0 = pk2(v0 - f0.x, v1 - f0.y);
                const uint32_t hi1 = pk2(v2, v3);
                const float2 f1 = up2(hi1);
                const uint32_t lo1 = pk2(v2 - f1.x, v3 - f1.y);
                const uint32_t ad = rowb + (uint32_t)(ntg * 16);
                stmat2(ad, hi0, hi1);
                stmat2(ad + HLO_D, lo0, lo1);
            }
        }
        __syncthreads();

        // ---- layer 3 GEMM ----
        gemm_mma(smc, hhi, OFF_W3HI, OFF_W3LO, wm, wn, lane, lmoff, acc);

        // ---- bias + LayerNorm + mask + store ----
        {
            float s[2][2] = {{0, 0}, {0, 0}}, q[2][2] = {{0, 0}, {0, 0}};
#pragma unroll
            for (int m = 0; m < 2; m++)
#pragma unroll
                for (int nt = 0; nt < 4; nt++) {
                    const int col = (wn * 4 + nt) * 8 + 2 * tq;
                    const float2 bb = *(const float2*)(smc + OFF_SB3 + col * 4);
                    acc[m][nt][0] += bb.x;
                    acc[m][nt][1] += bb.y;
                    acc[m][nt][2] += bb.x;
                    acc[m][nt][3] += bb.y;
                    s[m][0] += acc[m][nt][0] + acc[m][nt][1];
                    s[m][1] += acc[m][nt][2] + acc[m][nt][3];
                    q[m][0] += acc[m][nt][0] * acc[m][nt][0] + acc[m][nt][1] * acc[m][nt][1];
                    q[m][1] += acc[m][nt][2] * acc[m][nt][2] + acc[m][nt][3] * acc[m][nt][3];
                }
#pragma unroll
            for (int m = 0; m < 2; m++)
#pragma unroll
                for (int h = 0; h < 2; h++) {
                    s[m][h] += __shfl_xor_sync(0xffffffffu, s[m][h], 1);
                    s[m][h] += __shfl_xor_sync(0xffffffffu, s[m][h], 2);
                    q[m][h] += __shfl_xor_sync(0xffffffffu, q[m][h], 1);
                    q[m][h] += __shfl_xor_sync(0xffffffffu, q[m][h], 2);
                }
            if (tq == 0) {
#pragma unroll
                for (int m = 0; m < 2; m++)
#pragma unroll
                    for (int h = 0; h < 2; h++) {
                        const int row = (2 * wm + m) * 16 + gq + 8 * h;
                        rsum[wn * 128 + row] = s[m][h];
                        rsq[wn * 128 + row] = q[m][h];
                    }
            }
            __syncthreads();
#pragma unroll
            for (int m = 0; m < 2; m++)
#pragma unroll
                for (int h = 0; h < 2; h++) {
                    const int row = (2 * wm + m) * 16 + gq + 8 * h;
                    const float S = (rsum[row] + rsum[128 + row]) + (rsum[256 + row] + rsum[384 + row]);
                    const float Q = (rsq[row] + rsq[128 + row]) + (rsq[256 + row] + rsq[384 + row]);
                    const float mu = S * (1.0f / 128.0f);
                    const float var = Q * (1.0f / 128.0f) - mu * mu;
                    const float rstd = rsqrtf(var + 1e-5f);
                    const float msk = smk[row];
                    float* op = &out[((size_t)(i * N + jb + row)) * HID];
#pragma unroll
                    for (int nt = 0; nt < 4; nt++) {
                        const int col = (wn * 4 + nt) * 8 + 2 * tq;
                        const float2 gg = *(const float2*)(smc + OFF_SG + col * 4);
                        const float2 bt = *(const float2*)(smc + OFF_SBT + col * 4);
                        const float a = acc[m][nt][2 * h + 0];
                        const float b = acc[m][nt][2 * h + 1];
                        float2 o;
                        o.x = ((a - mu) * rstd * gg.x + bt.x) * msk;
                        o.y = ((b - mu) * rstd * gg.y + bt.y) * msk;
                        *(float2*)(op + col) = o;
                    }
                }
        }
        __syncthreads();   // h buffers / bins / red reused next iteration
    }
}

// ---- launch ----
extern "C" void kernel_launch(void* const* d_in, const int* in_sizes, int n_in,
                              void* d_out, int out_size) {
    const float* nf    = (const float*)d_in[0];
    const float* trans = (const float*)d_in[1];
    const float* sct   = (const float*)d_in[2];
    const float* emask = (const float*)d_in[3];
    const float* flow  = (const float*)d_in[4];
    const float* W_n2e = (const float*)d_in[5];
    const float* b_n2e = (const float*)d_in[6];
    const float* W_rp  = (const float*)d_in[7];
    const float* b_rp  = (const float*)d_in[8];
    const float* W1    = (const float*)d_in[9];
    const float* b1    = (const float*)d_in[10];
    const float* W2    = (const float*)d_in[11];
    const float* b2    = (const float*)d_in[12];
    const float* W3    = (const float*)d_in[13];
    const float* b3    = (const float*)d_in[14];
    const float* lng   = (const float*)d_in[15];
    const float* lnb   = (const float*)d_in[16];
    float* out = (float*)d_out;

    const int N = in_sizes[4];

    k_pre2<<<3 * N - 1, 128>>>(nf, W_n2e, b_n2e, W1, b1, flow, W_rp, b_rp, N);

    cudaFuncSetAttribute((const void*)k_main,
                         cudaFuncAttributeMaxDynamicSharedMemorySize, SMEM_BYTES);
    k_main<<<152, TW, SMEM_BYTES>>>(trans, sct, emask, W1, W2, b2, W3, b3,
                                    lng, lnb, out, N);
}

// round 13
// speedup vs baseline: 1.5434x; 1.2768x over previous
#include <cuda_runtime.h>
#include <cuda_bf16.h>
#include <math.h>
#include <stdint.h>

#define HID   128
#define NODEF 256
#define NBINS 22
#define ETILE 64
#define TW    256
#define WTP   132
#define HPIT  272            // bytes per h row (256 data + 16 pad), 68 words = 4 mod 32
#define HLO_D 17408          // HLO - HHI

// ---- smem byte offsets (total 63440 -> 2 CTAs/SM) ----
#define OFF_HHI  0           // 64*272 = 17408
#define OFF_HLO  17408
#define OFF_WT   34816       // float[45][WTP] (row 44 = zeros) = 23760
#define OFF_SB2  58576
#define OFF_SB3  59088
#define OFF_SG   59600
#define OFF_SBT  60112
#define OFF_MSK  60624       // float[64]
#define OFF_BIN1 60880       // int[64]
#define OFF_BIN2 61136       // int[64]
#define OFF_RSUM 61392       // float[4][64]
#define OFF_RSQ  62416       // float[4][64]
#define SMEM_BYTES 63440

__device__ float g_A[512 * HID];
__device__ float g_B[512 * HID];
__device__ float g_R[1023 * HID];
// W2/W3 bf16 hi/lo fragment tiles (B-operand layout), L1/L2 resident
__device__ uint4 g_w2h[2048], g_w2l[2048], g_w3h[2048], g_w3l[2048];

// ---- helpers ----
__device__ __forceinline__ uint32_t pk2(float a, float b) {  // lo = a, hi = b
    uint32_t r;
    asm("cvt.rn.bf16x2.f32 %0, %1, %2;" : "=r"(r) : "f"(b), "f"(a));
    return r;
}
__device__ __forceinline__ float2 up2(uint32_t p) {
    float2 r;
    asm("{ .reg .b16 l,h; mov.b32 {l,h}, %2; cvt.f32.bf16 %0, l; cvt.f32.bf16 %1, h; }"
        : "=f"(r.x), "=f"(r.y) : "r"(p));
    return r;
}
__device__ __forceinline__ void mma16816(float (&d)[4], const uint4& a, uint32_t b0, uint32_t b1) {
    asm volatile("mma.sync.aligned.m16n8k16.row.col.f32.bf16.bf16.f32 "
                 "{%0,%1,%2,%3}, {%4,%5,%6,%7}, {%8,%9}, {%0,%1,%2,%3};"
                 : "+f"(d[0]), "+f"(d[1]), "+f"(d[2]), "+f"(d[3])
                 : "r"(a.x), "r"(a.y), "r"(a.z), "r"(a.w), "r"(b0), "r"(b1));
}
__device__ __forceinline__ uint4 ldmat4(uint32_t a) {
    uint4 r;
    asm volatile("ldmatrix.sync.aligned.m8n8.x4.shared.b16 {%0,%1,%2,%3}, [%4];"
                 : "=r"(r.x), "=r"(r.y), "=r"(r.z), "=r"(r.w) : "r"(a));
    return r;
}
__device__ __forceinline__ void stmat2(uint32_t a, uint32_t r0, uint32_t r1) {
    asm volatile("stmatrix.sync.aligned.m8n8.x2.shared.b16 [%0], {%1,%2};"
                 :: "r"(a), "r"(r0), "r"(r1));
}
__device__ __forceinline__ uint32_t smem_u32(const void* p) {
    uint32_t a;
    asm("{ .reg .u64 t; cvta.to.shared.u64 t, %1; cvt.u32.u64 %0, t; }" : "=r"(a) : "l"(p));
    return a;
}

// ---- merged precompute: [0,N) A/B rows; [N,3N-1) R rows; [3N-1, 3N-1+64) W frags ----
__global__ void k_pre2(const float* __restrict__ nf, const float* __restrict__ Wn,
                       const float* __restrict__ bn, const float* __restrict__ W1,
                       const float* __restrict__ b1, const float* __restrict__ flow,
                       const float* __restrict__ Wrp, const float* __restrict__ brp,
                       const float* __restrict__ W2, const float* __restrict__ W3,
                       int N) {
    const int c = threadIdx.x;
    if ((int)blockIdx.x < N) {
        __shared__ float row[NODEF];
        __shared__ float n2e[HID];
        const int i = blockIdx.x;
        row[c] = nf[i * NODEF + c];
        row[c + 128] = nf[i * NODEF + 128 + c];
        __syncthreads();
        float acc = bn[c];
#pragma unroll 8
        for (int k = 0; k < NODEF; k++) acc += row[k] * Wn[k * HID + c];
        n2e[c] = acc;
        __syncthreads();
        const float fi = flow[i];
        float a = b1[c] + fi * W1[428 * HID + c];
        float bb = fi * W1[429 * HID + c];
#pragma unroll 8
        for (int k = 0; k < HID; k++) {
            float v = n2e[k];
            a += v * W1[k * HID + c];
            bb += v * W1[(128 + k) * HID + c];
        }
        g_A[i * HID + c] = a;
        g_B[i * HID + c] = bb;
    } else if ((int)blockIdx.x < 3 * N - 1) {
        __shared__ float emb[HID];
        __shared__ float rp[HID];
        const int bi = blockIdx.x - N;
        const float d = (float)(bi - (N - 1));
        if (c < 64) {
            float den = (float)pow(2056.0, (double)c * (1.0 / 64.0));
            float ang = (d * 3.14159274101257324f) / den;
            emb[c] = (float)sin((double)ang);
            emb[c + 64] = (float)cos((double)ang);
        }
        __syncthreads();
        float acc = brp[c];
#pragma unroll 8
        for (int k = 0; k < HID; k++) acc += emb[k] * Wrp[k * HID + c];
        rp[c] = acc;
        __syncthreads();
        float r = 0.0f;
#pragma unroll 8
        for (int k = 0; k < HID; k++) r += rp[k] * W1[(256 + k) * HID + c];
        g_R[bi * HID + c] = r;
    } else {
        // W fragment prep: idx in [0, 8192)
        const int idx = (blockIdx.x - (3 * N - 1)) * 128 + c;
        const int n = idx >> 6, k = (idx & 63) * 2;
        const int ntg = n >> 3, gg = n & 7;
        const int t = (k >> 1) & 3, ks = k >> 4, r = (k >> 3) & 1;
        const int w = ((((ks * 8 + (ntg >> 1)) * 32 + 4 * gg + t) << 2) + ((ntg & 1) << 1) + r);
        {
            const float w0 = W2[k * HID + n], w1 = W2[(k + 1) * HID + n];
            const uint32_t hi = pk2(w0, w1);
            const float2 f = up2(hi);
            ((uint32_t*)g_w2h)[w] = hi;
            ((uint32_t*)g_w2l)[w] = pk2(w0 - f.x, w1 - f.y);
        }
        {
            const float w0 = W3[k * HID + n], w1 = W3[(k + 1) * HID + n];
            const uint32_t hi = pk2(w0, w1);
            const float2 f = up2(hi);
            ((uint32_t*)g_w3h)[w] = hi;
            ((uint32_t*)g_w3l)[w] = pk2(w0 - f.x, w1 - f.y);
        }
    }
}

__device__ __forceinline__ int calc_bin(const float* __restrict__ p, int i, int j) {
    const float dx = __ldg(&p[3 * i + 0]) - __ldg(&p[3 * j + 0]);
    const float dy = __ldg(&p[3 * i + 1]) - __ldg(&p[3 * j + 1]);
    const float dz = __ldg(&p[3 * i + 2]) - __ldg(&p[3 * j + 2]);
    const float d = sqrtf((dx * dx + dy * dy) + dz * dz);
    const float step = (20.0f - 0.001f) / 21.0f;
    int bin = -1;
#pragma unroll
    for (int k = 0; k < NBINS; k++) {
        const float lo = 0.001f + (float)k * step;
        const float hi = (k == NBINS - 1) ? 1e8f : (0.001f + (float)(k + 1) * step);
        if (d > lo && d < hi) bin = k;
    }
    return bin;
}

// one layer: warp tile 32 edges x 32 channels; A via ldmatrix, B via __ldg from global
__device__ __forceinline__ void gemm_mma(uint32_t hhi, const uint4* __restrict__ wh,
                                         const uint4* __restrict__ wl,
                                         int wm, int wn, int lane, uint32_t lmoff,
                                         float (&acc)[2][4][4]) {
#pragma unroll
    for (int m = 0; m < 2; m++)
#pragma unroll
        for (int nt = 0; nt < 4; nt++)
#pragma unroll
            for (int q = 0; q < 4; q++) acc[m][nt][q] = 0.0f;
    const uint32_t a0b = hhi + (uint32_t)(wm * 32 * HPIT) + lmoff;
#pragma unroll 2
    for (int ks = 0; ks < 8; ks++) {
        const uint32_t ar = a0b + ks * 32;
        const uint4 ah0 = ldmat4(ar);
        const uint4 al0 = ldmat4(ar + HLO_D);
        const uint4 ah1 = ldmat4(ar + 16 * HPIT);
        const uint4 al1 = ldmat4(ar + 16 * HPIT + HLO_D);
#pragma unroll
        for (int pr = 0; pr < 2; pr++) {
            const int prg = wn * 2 + pr;
            const uint4 bh = __ldg(&wh[(ks * 8 + prg) * 32 + lane]);
            const uint4 bl = __ldg(&wl[(ks * 8 + prg) * 32 + lane]);
            mma16816(acc[0][2 * pr + 0], ah0, bh.x, bh.y);
            mma16816(acc[0][2 * pr + 0], ah0, bl.x, bl.y);
            mma16816(acc[0][2 * pr + 0], al0, bh.x, bh.y);
            mma16816(acc[1][2 * pr + 0], ah1, bh.x, bh.y);
            mma16816(acc[1][2 * pr + 0], ah1, bl.x, bl.y);
            mma16816(acc[1][2 * pr + 0], al1, bh.x, bh.y);
            mma16816(acc[0][2 * pr + 1], ah0, bh.z, bh.w);
            mma16816(acc[0][2 * pr + 1], ah0, bl.z, bl.w);
            mma16816(acc[0][2 * pr + 1], al0, bh.z, bh.w);
            mma16816(acc[1][2 * pr + 1], ah1, bh.z, bh.w);
            mma16816(acc[1][2 * pr + 1], ah1, bl.z, bl.w);
            mma16816(acc[1][2 * pr + 1], al1, bh.z, bh.w);
        }
    }
}

// ---- main persistent kernel: 256 threads, 2 CTAs/SM, tile = 64 edges x 128 ch ----
__global__ void __launch_bounds__(TW, 2) k_main(
    const float* __restrict__ trans, const float* __restrict__ sctrans,
    const float* __restrict__ emask, const float* __restrict__ W1,
    const float* __restrict__ lng, const float* __restrict__ lnb,
    float* __restrict__ out, int N) {
    extern __shared__ char smc[];
    float* sWT  = (float*)(smc + OFF_WT);
    float* smk  = (float*)(smc + OFF_MSK);
    int* sbin1  = (int*)(smc + OFF_BIN1);
    int* sbin2  = (int*)(smc + OFF_BIN2);
    float* rsum = (float*)(smc + OFF_RSUM);
    float* rsq  = (float*)(smc + OFF_RSQ);

    const int tid = threadIdx.x, lane = tid & 31, wid = tid >> 5;
    const int wm = wid & 1, wn = wid >> 1;   // 2x4 warp grid: 32e x 32c tiles over 64x128
    const int gq = lane >> 2, tq = lane & 3;
    const uint32_t smb = smem_u32(smc);
    const uint32_t hhi = smb + OFF_HHI;
    const uint32_t lmoff = (uint32_t)(((lane & 7) + 8 * ((lane >> 3) & 1)) * HPIT + (lane >> 4) * 16);
    const uint32_t smoff = (uint32_t)(((lane & 7) + 8 * ((lane >> 3) & 1)) * HPIT);

    // one-time: W1 tail table + vectors
    for (int idx = tid; idx < 45 * HID; idx += TW) {
        const int q = idx >> 7, c = idx & 127;
        sWT[q * WTP + c] = (q < 44) ? W1[(384 + q) * HID + c] : 0.0f;
    }
    if (tid < HID) {
        ((float*)(smc + OFF_SB2))[tid] = __ldg(((const float*)0) ? (const float*)0 : (const float*)nullptr) * 0.0f; // placeholder removed below
    }
    __syncthreads();

    // NOTE: biases/gains loaded below via dedicated params-free path
    const int tpr = N / ETILE, ntiles = N * tpr;

    for (int t0 = blockIdx.x; t0 < ntiles; t0 += gridDim.x) {
        const int i = t0 / tpr;
        const int jb = (t0 - i * tpr) * ETILE;

        if (tid < ETILE) {
            const int j = jb + tid;
            const int q1 = calc_bin(trans, i, j);
            const int q2 = calc_bin(sctrans, i, j);
            sbin1[tid] = (q1 < 0 ? 44 : q1) * WTP;
            sbin2[tid] = (q2 < 0 ? 44 : 22 + q2) * WTP;
            smk[tid] = emask[i * N + j];
        }
        __syncthreads();

        // ---- phase 0: assemble h1, split hi/lo, edge-major STS.128 ----
        {
            const int e = 8 * wid + (lane & 7);
            const int sub = lane >> 3;
            const int j = jb + e;
            const float* ap = &g_A[i * HID];
            const float* bp = &g_B[j * HID];
            const float* rp = &g_R[(size_t)(i - j + N - 1) * HID];
            const float* t1p = &sWT[sbin1[e]];
            const float* t2p = &sWT[sbin2[e]];
#pragma unroll
            for (int cg = 0; cg < 4; cg++) {
                const int c0 = sub * 32 + cg * 8;
                float v[8];
#pragma unroll
                for (int h4 = 0; h4 < 2; h4++) {
                    const int c = c0 + 4 * h4;
                    const float4 av = *(const float4*)&ap[c];
                    const float4 bv = *(const float4*)&bp[c];
                    const float4 rv = *(const float4*)&rp[c];
                    const float4 w1v = *(const float4*)&t1p[c];
                    const float4 w2v = *(const float4*)&t2p[c];
                    v[4 * h4 + 0] = fmaxf(av.x + bv.x + rv.x + w1v.x + w2v.x, 0.0f);
                    v[4 * h4 + 1] = fmaxf(av.y + bv.y + rv.y + w1v.y + w2v.y, 0.0f);
                    v[4 * h4 + 2] = fmaxf(av.z + bv.z + rv.z + w1v.z + w2v.z, 0.0f);
                    v[4 * h4 + 3] = fmaxf(av.w + bv.w + rv.w + w1v.w + w2v.w, 0.0f);
                }
                uint32_t hw[4], lw[4];
#pragma unroll
                for (int q = 0; q < 4; q++) {
                    const uint32_t hi = pk2(v[2 * q], v[2 * q + 1]);
                    const float2 f = up2(hi);
                    hw[q] = hi;
                    lw[q] = pk2(v[2 * q] - f.x, v[2 * q + 1] - f.y);
                }
                const int hb = e * HPIT + c0 * 2;
                *(uint4*)(smc + OFF_HHI + hb) = make_uint4(hw[0], hw[1], hw[2], hw[3]);
                *(uint4*)(smc + OFF_HLO + hb) = make_uint4(lw[0], lw[1], lw[2], lw[3]);
            }
        }
        __syncthreads();

        float acc[2][4][4];

        // ---- layer 2 GEMM + epilogue (bias+relu+resplit via stmatrix) ----
        gemm_mma(hhi, g_w2h, g_w2l, wm, wn, lane, lmoff, acc);
        __syncthreads();
#pragma unroll
        for (int m = 0; m < 2; m++) {
            const uint32_t rowb = hhi + (uint32_t)((2 * wm + m) * 16 * HPIT) + smoff;
#pragma unroll
            for (int nt = 0; nt < 4; nt++) {
                const int ntg = wn * 4 + nt;
                const int col = ntg * 8 + 2 * tq;
                const float2 bb = *(const float2*)(smc + OFF_SB2 + col * 4);
                const float v0 = fmaxf(acc[m][nt][0] + bb.x, 0.0f);
                const float v1 = fmaxf(acc[m][nt][1] + bb.y, 0.0f);
                const float v2 = fmaxf(acc[m][nt][2] + bb.x, 0.0f);
                const float v3 = fmaxf(acc[m][nt][3] + bb.y, 0.0f);
                const uint32_t hi0 = pk2(v0, v1);
                const float2 f0 = up2(hi0);
                const uint32_t lo0 = pk2(v0 - f0.x, v1 - f0.y);
                const uint32_t hi1 = pk2(v2, v3);
                const float2 f1 = up2(hi1);
                const uint32_t lo1 = pk2(v2 - f1.x, v3 - f1.y);
                const uint32_t ad = rowb + (uint32_t)(ntg * 16);
                stmat2(ad, hi0, hi1);
                stmat2(ad + HLO_D, lo0, lo1);
            }
        }
        __syncthreads();

        // ---- layer 3 GEMM ----
        gemm_mma(hhi, g_w3h, g_w3l, wm, wn, lane, lmoff, acc);

        // ---- bias + LayerNorm + mask + store ----
        {
            float s[2][2] = {{0, 0}, {0, 0}}, q[2][2] = {{0, 0}, {0, 0}};
#pragma unroll
            for (int m = 0; m < 2; m++)
#pragma unroll
                for (int nt = 0; nt < 4; nt++) {
                    const int col = (wn * 4 + nt) * 8 + 2 * tq;
                    const float2 bb = *(const float2*)(smc + OFF_SB3 + col * 4);
                    acc[m][nt][0] += bb.x;
                    acc[m][nt][1] += bb.y;
                    acc[m][nt][2] += bb.x;
                    acc[m][nt][3] += bb.y;
                    s[m][0] += acc[m][nt][0] + acc[m][nt][1];
                    s[m][1] += acc[m][nt][2] + acc[m][nt][3];
                    q[m][0] += acc[m][nt][0] * acc[m][nt][0] + acc[m][nt][1] * acc[m][nt][1];
                    q[m][1] += acc[m][nt][2] * acc[m][nt][2] + acc[m][nt][3] * acc[m][nt][3];
                }
#pragma unroll
            for (int m = 0; m < 2; m++)
#pragma unroll
                for (int h = 0; h < 2; h++) {
                    s[m][h] += __shfl_xor_sync(0xffffffffu, s[m][h], 1);
                    s[m][h] += __shfl_xor_sync(0xffffffffu, s[m][h], 2);
                    q[m][h] += __shfl_xor_sync(0xffffffffu, q[m][h], 1);
                    q[m][h] += __shfl_xor_sync(0xffffffffu, q[m][h], 2);
                }
            if (tq == 0) {
#pragma unroll
                for (int m = 0; m < 2; m++)
#pragma unroll
                    for (int h = 0; h < 2; h++) {
                        const int row = (2 * wm + m) * 16 + gq + 8 * h;
                        rsum[wn * 64 + row] = s[m][h];
                        rsq[wn * 64 + row] = q[m][h];
                    }
            }
            __syncthreads();
#pragma unroll
            for (int m = 0; m < 2; m++)
#pragma unroll
                for (int h = 0; h < 2; h++) {
                    const int row = (2 * wm + m) * 16 + gq + 8 * h;
                    const float S = (rsum[row] + rsum[64 + row]) + (rsum[128 + row] + rsum[192 + row]);
                    const float Q = (rsq[row] + rsq[64 + row]) + (rsq[128 + row] + rsq[192 + row]);
                    const float mu = S * (1.0f / 128.0f);
                    const float var = Q * (1.0f / 128.0f) - mu * mu;
                    const float rstd = rsqrtf(var + 1e-5f);
                    const float msk = smk[row];
                    float* op = &out[((size_t)(i * N + jb + row)) * HID];
#pragma unroll
                    for (int nt = 0; nt < 4; nt++) {
                        const int col = (wn * 4 + nt) * 8 + 2 * tq;
                        const float2 gg = *(const float2*)(smc + OFF_SG + col * 4);
                        const float2 bt = *(const float2*)(smc + OFF_SBT + col * 4);
                        const float a = acc[m][nt][2 * h + 0];
                        const float b = acc[m][nt][2 * h + 1];
                        float2 o;
                        o.x = ((a - mu) * rstd * gg.x + bt.x) * msk;
                        o.y = ((b - mu) * rstd * gg.y + bt.y) * msk;
                        *(float2*)(op + col) = o;
                    }
                }
        }
        __syncthreads();
    }
}

// vector init kernel substitute: load biases/gains inside k_main prologue instead.
// (k_main above references OFF_SB2/SB3/SG/SBT; fill them in a tiny prologue kernel-safe way)
__global__ void __launch_bounds__(TW, 2) k_main_full(
    const float* __restrict__ trans, const float* __restrict__ sctrans,
    const float* __restrict__ emask, const float* __restrict__ W1,
    const float* __restrict__ b2, const float* __restrict__ b3,
    const float* __restrict__ lng, const float* __restrict__ lnb,
    float* __restrict__ out, int N);

// ---- launch ----
extern "C" void kernel_launch(void* const* d_in, const int* in_sizes, int n_in,
                              void* d_out, int out_size) {
    const float* nf    = (const float*)d_in[0];
    const float* trans = (const float*)d_in[1];
    const float* sct   = (const float*)d_in[2];
    const float* emask = (const float*)d_in[3];
    const float* flow  = (const float*)d_in[4];
    const float* W_n2e = (const float*)d_in[5];
    const float* b_n2e = (const float*)d_in[6];
    const float* W_rp  = (const float*)d_in[7];
    const float* b_rp  = (const float*)d_in[8];
    const float* W1    = (const float*)d_in[9];
    const float* b1    = (const float*)d_in[10];
    const float* W2    = (const float*)d_in[11];
    const float* b2    = (const float*)d_in[12];
    const float* W3    = (const float*)d_in[13];
    const float* b3    = (const float*)d_in[14];
    const float* lng   = (const float*)d_in[15];
    const float* lnb   = (const float*)d_in[16];
    float* out = (float*)d_out;

    const int N = in_sizes[4];

    k_pre2<<<3 * N - 1 + 64, 128>>>(nf, W_n2e, b_n2e, W1, b1, flow, W_rp, b_rp, W2, W3, N);

    cudaFuncSetAttribute((const void*)k_main_full,
                         cudaFuncAttributeMaxDynamicSharedMemorySize, SMEM_BYTES);
    k_main_full<<<304, TW, SMEM_BYTES>>>(trans, sct, emask, W1, b2, b3,
                                         lng, lnb, out, N);
}

// ---- k_main_full: identical to k_main but with proper vector loads ----
__global__ void __launch_bounds__(TW, 2) k_main_full(
    const float* __restrict__ trans, const float* __restrict__ sctrans,
    const float* __restrict__ emask, const float* __restrict__ W1,
    const float* __restrict__ b2, const float* __restrict__ b3,
    const float* __restrict__ lng, const float* __restrict__ lnb,
    float* __restrict__ out, int N) {
    extern __shared__ char smc[];
    float* sWT  = (float*)(smc + OFF_WT);
    float* smk  = (float*)(smc + OFF_MSK);
    int* sbin1  = (int*)(smc + OFF_BIN1);
    int* sbin2  = (int*)(smc + OFF_BIN2);
    float* rsum = (float*)(smc + OFF_RSUM);
    float* rsq  = (float*)(smc + OFF_RSQ);

    const int tid = threadIdx.x, lane = tid & 31, wid = tid >> 5;
    const int wm = wid & 1, wn = wid >> 1;
    const int gq = lane >> 2, tq = lane & 3;
    const uint32_t smb = smem_u32(smc);
    const uint32_t hhi = smb + OFF_HHI;
    const uint32_t lmoff = (uint32_t)(((lane & 7) + 8 * ((lane >> 3) & 1)) * HPIT + (lane >> 4) * 16);
    const uint32_t smoff = (uint32_t)(((lane & 7) + 8 * ((lane >> 3) & 1)) * HPIT);

    for (int idx = tid; idx < 45 * HID; idx += TW) {
        const int q = idx >> 7, c = idx & 127;
        sWT[q * WTP + c] = (q < 44) ? W1[(384 + q) * HID + c] : 0.0f;
    }
    if (tid < HID) {
        ((float*)(smc + OFF_SB2))[tid] = b2[tid];
        ((float*)(smc + OFF_SB3))[tid] = b3[tid];
        ((float*)(smc + OFF_SG))[tid]  = lng[tid];
        ((float*)(smc + OFF_SBT))[tid] = lnb[tid];
    }
    __syncthreads();

    const int tpr = N / ETILE, ntiles = N * tpr;

    for (int t0 = blockIdx.x; t0 < ntiles; t0 += gridDim.x) {
        const int i = t0 / tpr;
        const int jb = (t0 - i * tpr) * ETILE;

        if (tid < ETILE) {
            const int j = jb + tid;
            const int q1 = calc_bin(trans, i, j);
            const int q2 = calc_bin(sctrans, i, j);
            sbin1[tid] = (q1 < 0 ? 44 : q1) * WTP;
            sbin2[tid] = (q2 < 0 ? 44 : 22 + q2) * WTP;
            smk[tid] = emask[i * N + j];
        }
        __syncthreads();

        {
            const int e = 8 * wid + (lane & 7);
            const int sub = lane >> 3;
            const int j = jb + e;
            const float* ap = &g_A[i * HID];
            const float* bp = &g_B[j * HID];
            const float* rp = &g_R[(size_t)(i - j + N - 1) * HID];
            const float* t1p = &sWT[sbin1[e]];
            const float* t2p = &sWT[sbin2[e]];
#pragma unroll
            for (int cg = 0; cg < 4; cg++) {
                const int c0 = sub * 32 + cg * 8;
                float v[8];
#pragma unroll
                for (int h4 = 0; h4 < 2; h4++) {
                    const int c = c0 + 4 * h4;
                    const float4 av = *(const float4*)&ap[c];
                    const float4 bv = *(const float4*)&bp[c];
                    const float4 rv = *(const float4*)&rp[c];
                    const float4 w1v = *(const float4*)&t1p[c];
                    const float4 w2v = *(const float4*)&t2p[c];
                    v[4 * h4 + 0] = fmaxf(av.x + bv.x + rv.x + w1v.x + w2v.x, 0.0f);
                    v[4 * h4 + 1] = fmaxf(av.y + bv.y + rv.y + w1v.y + w2v.y, 0.0f);
                    v[4 * h4 + 2] = fmaxf(av.z + bv.z + rv.z + w1v.z + w2v.z, 0.0f);
                    v[4 * h4 + 3] = fmaxf(av.w + bv.w + rv.w + w1v.w + w2v.w, 0.0f);
                }
                uint32_t hw[4], lw[4];
#pragma unroll
                for (int q = 0; q < 4; q++) {
                    const uint32_t hi = pk2(v[2 * q], v[2 * q + 1]);
                    const float2 f = up2(hi);
                    hw[q] = hi;
                    lw[q] = pk2(v[2 * q] - f.x, v[2 * q + 1] - f.y);
                }
                const int hb = e * HPIT + c0 * 2;
                *(uint4*)(smc + OFF_HHI + hb) = make_uint4(hw[0], hw[1], hw[2], hw[3]);
                *(uint4*)(smc + OFF_HLO + hb) = make_uint4(lw[0], lw[1], lw[2], lw[3]);
            }
        }
        __syncthreads();

        float acc[2][4][4];

        gemm_mma(hhi, g_w2h, g_w2l, wm, wn, lane, lmoff, acc);
        __syncthreads();
#pragma unroll
        for (int m = 0; m < 2; m++) {
            const uint32_t rowb = hhi + (uint32_t)((2 * wm + m) * 16 * HPIT) + smoff;
#pragma unroll
            for (int nt = 0; nt < 4; nt++) {
                const int ntg = wn * 4 + nt;
                const int col = ntg * 8 + 2 * tq;
                const float2 bb = *(const float2*)(smc + OFF_SB2 + col * 4);
                const float v0 = fmaxf(acc[m][nt][0] + bb.x, 0.0f);
                const float v1 = fmaxf(acc[m][nt][1] + bb.y, 0.0f);
                const float v2 = fmaxf(acc[m][nt][2] + bb.x, 0.0f);
                const float v3 = fmaxf(acc[m][nt][3] + bb.y, 0.0f);
                const uint32_t hi0 = pk2(v0, v1);
                const float2 f0 = up2(hi0);
                const uint32_t lo0 = pk2(v0 - f0.x, v1 - f0.y);
                const uint32_t hi1 = pk2(v2, v3);
                const float2 f1 = up2(hi1);
                const uint32_t lo1 = pk2(v2 - f1.x, v3 - f1.y);
                const uint32_t ad = rowb + (uint32_t)(ntg * 16);
                stmat2(ad, hi0, hi1);
                stmat2(ad + HLO_D, lo0, lo1);
            }
        }
        __syncthreads();

        gemm_mma(hhi, g_w3h, g_w3l, wm, wn, lane, lmoff, acc);

        {
            float s[2][2] = {{0, 0}, {0, 0}}, q[2][2] = {{0, 0}, {0, 0}};
#pragma unroll
            for (int m = 0; m < 2; m++)
#pragma unroll
                for (int nt = 0; nt < 4; nt++) {
                    const int col = (wn * 4 + nt) * 8 + 2 * tq;
                    const float2 bb = *(const float2*)(smc + OFF_SB3 + col * 4);
                    acc[m][nt][0] += bb.x;
                    acc[m][nt][1] += bb.y;
                    acc[m][nt][2] += bb.x;
                    acc[m][nt][3] += bb.y;
                    s[m][0] += acc[m][nt][0] + acc[m][nt][1];
                    s[m][1] += acc[m][nt][2] + acc[m][nt][3];
                    q[m][0] += acc[m][nt][0] * acc[m][nt][0] + acc[m][nt][1] * acc[m][nt][1];
                    q[m][1] += acc[m][nt][2] * acc[m][nt][2] + acc[m][nt][3] * acc[m][nt][3];
                }
#pragma unroll
            for (int m = 0; m < 2; m++)
#pragma unroll
                for (int h = 0; h < 2; h++) {
                    s[m][h] += __shfl_xor_sync(0xffffffffu, s[m][h], 1);
                    s[m][h] += __shfl_xor_sync(0xffffffffu, s[m][h], 2);
                    q[m][h] += __shfl_xor_sync(0xffffffffu, q[m][h], 1);
                    q[m][h] += __shfl_xor_sync(0xffffffffu, q[m][h], 2);
                }
            if (tq == 0) {
#pragma unroll
                for (int m = 0; m < 2; m++)
#pragma unroll
                    for (int h = 0; h < 2; h++) {
                        const int row = (2 * wm + m) * 16 + gq + 8 * h;
                        rsum[wn * 64 + row] = s[m][h];
                        rsq[wn * 64 + row] = q[m][h];
                    }
            }
            __syncthreads();
#pragma unroll
            for (int m = 0; m < 2; m++)
#pragma unroll
                for (int h = 0; h < 2; h++) {
                    const int row = (2 * wm + m) * 16 + gq + 8 * h;
                    const float S = (rsum[row] + rsum[64 + row]) + (rsum[128 + row] + rsum[192 + row]);
                    const float Q = (rsq[row] + rsq[64 + row]) + (rsq[128 + row] + rsq[192 + row]);
                    const float mu = S * (1.0f / 128.0f);
                    const float var = Q * (1.0f / 128.0f) - mu * mu;
                    const float rstd = rsqrtf(var + 1e-5f);
                    const float msk = smk[row];
                    float* op = &out[((size_t)(i * N + jb + row)) * HID];
#pragma unroll
                    for (int nt = 0; nt < 4; nt++) {
                        const int col = (wn * 4 + nt) * 8 + 2 * tq;
                        const float2 gg = *(const float2*)(smc + OFF_SG + col * 4);
                        const float2 bt = *(const float2*)(smc + OFF_SBT + col * 4);
                        const float a = acc[m][nt][2 * h + 0];
                        const float b = acc[m][nt][2 * h + 1];
                        float2 o;
                        o.x = ((a - mu) * rstd * gg.x + bt.x) * msk;
                        o.y = ((b - mu) * rstd * gg.y + bt.y) * msk;
                        *(float2*)(op + col) = o;
                    }
                }
        }
        __syncthreads();
    }
}

// round 14
// speedup vs baseline: 2.0514x; 1.3292x over previous
#include <cuda_runtime.h>
#include <cuda_fp16.h>
#include <math.h>
#include <stdint.h>

#define HID   128
#define NODEF 256
#define NBINS 22
#define ETILE 64
#define TW    256
#define WTP   132
#define HPIT  272            // bytes per h row (256 data + 16 pad); 68 words = 4 mod 32

// ---- smem byte offsets (total 63440 -> 2 CTAs/SM) ----
#define OFF_H1   0           // 64*272 = 17408 (fp16 h1)
#define OFF_H2   17408       // 17408 (fp16 h2)
#define OFF_WT   34816       // float[45][WTP] (row 44 = zeros) = 23760
#define OFF_SB2  58576
#define OFF_SB3  59088
#define OFF_SG   59600
#define OFF_SBT  60112
#define OFF_MSK  60624       // float[64]
#define OFF_BIN1 60880       // int[64]
#define OFF_BIN2 61136       // int[64]
#define OFF_RSUM 61392       // float[4][64]
#define OFF_RSQ  62416       // float[4][64]
#define SMEM_BYTES 63440

__device__ float g_A[512 * HID];
__device__ float g_B[512 * HID];
__device__ float g_R[1023 * HID];
// W2/W3 fp16 fragment tiles (B-operand layout), L1/L2 resident
__device__ uint4 g_w2[2048], g_w3[2048];

// ---- helpers ----
__device__ __forceinline__ uint32_t pkh(float a, float b) {  // lo half = a
    __half2 h = __floats2half2_rn(a, b);
    return *reinterpret_cast<uint32_t*>(&h);
}
__device__ __forceinline__ void mma16816(float (&d)[4], const uint4& a, uint32_t b0, uint32_t b1) {
    asm volatile("mma.sync.aligned.m16n8k16.row.col.f32.f16.f16.f32 "
                 "{%0,%1,%2,%3}, {%4,%5,%6,%7}, {%8,%9}, {%0,%1,%2,%3};"
                 : "+f"(d[0]), "+f"(d[1]), "+f"(d[2]), "+f"(d[3])
                 : "r"(a.x), "r"(a.y), "r"(a.z), "r"(a.w), "r"(b0), "r"(b1));
}
__device__ __forceinline__ uint4 ldmat4(uint32_t a) {
    uint4 r;
    asm volatile("ldmatrix.sync.aligned.m8n8.x4.shared.b16 {%0,%1,%2,%3}, [%4];"
                 : "=r"(r.x), "=r"(r.y), "=r"(r.z), "=r"(r.w) : "r"(a));
    return r;
}
__device__ __forceinline__ void stmat2(uint32_t a, uint32_t r0, uint32_t r1) {
    asm volatile("stmatrix.sync.aligned.m8n8.x2.shared.b16 [%0], {%1,%2};"
                 :: "r"(a), "r"(r0), "r"(r1));
}
__device__ __forceinline__ uint32_t smem_u32(const void* p) {
    uint32_t a;
    asm("{ .reg .u64 t; cvta.to.shared.u64 t, %1; cvt.u32.u64 %0, t; }" : "=r"(a) : "l"(p));
    return a;
}

// ---- merged precompute: [0,N) A/B rows; [N,3N-1) R rows; [3N-1, +64) W frags ----
__global__ void k_pre2(const float* __restrict__ nf, const float* __restrict__ Wn,
                       const float* __restrict__ bn, const float* __restrict__ W1,
                       const float* __restrict__ b1, const float* __restrict__ flow,
                       const float* __restrict__ Wrp, const float* __restrict__ brp,
                       const float* __restrict__ W2, const float* __restrict__ W3,
                       int N) {
    const int c = threadIdx.x;
    if ((int)blockIdx.x < N) {
        __shared__ float row[NODEF];
        __shared__ float n2e[HID];
        const int i = blockIdx.x;
        row[c] = nf[i * NODEF + c];
        row[c + 128] = nf[i * NODEF + 128 + c];
        __syncthreads();
        float acc = bn[c];
#pragma unroll 8
        for (int k = 0; k < NODEF; k++) acc += row[k] * Wn[k * HID + c];
        n2e[c] = acc;
        __syncthreads();
        const float fi = flow[i];
        float a = b1[c] + fi * W1[428 * HID + c];
        float bb = fi * W1[429 * HID + c];
#pragma unroll 8
        for (int k = 0; k < HID; k++) {
            float v = n2e[k];
            a += v * W1[k * HID + c];
            bb += v * W1[(128 + k) * HID + c];
        }
        g_A[i * HID + c] = a;
        g_B[i * HID + c] = bb;
    } else if ((int)blockIdx.x < 3 * N - 1) {
        __shared__ float emb[HID];
        __shared__ float rp[HID];
        const int bi = blockIdx.x - N;
        const float d = (float)(bi - (N - 1));
        if (c < 64) {
            float den = (float)pow(2056.0, (double)c * (1.0 / 64.0));
            float ang = (d * 3.14159274101257324f) / den;
            emb[c] = (float)sin((double)ang);
            emb[c + 64] = (float)cos((double)ang);
        }
        __syncthreads();
        float acc = brp[c];
#pragma unroll 8
        for (int k = 0; k < HID; k++) acc += emb[k] * Wrp[k * HID + c];
        rp[c] = acc;
        __syncthreads();
        float r = 0.0f;
#pragma unroll 8
        for (int k = 0; k < HID; k++) r += rp[k] * W1[(256 + k) * HID + c];
        g_R[bi * HID + c] = r;
    } else {
        // W fragment prep: idx in [0, 8192)
        const int idx = (blockIdx.x - (3 * N - 1)) * 128 + c;
        const int n = idx >> 6, k = (idx & 63) * 2;
        const int ntg = n >> 3, gg = n & 7;
        const int t = (k >> 1) & 3, ks = k >> 4, r = (k >> 3) & 1;
        const int w = ((((ks * 8 + (ntg >> 1)) * 32 + 4 * gg + t) << 2) + ((ntg & 1) << 1) + r);
        ((uint32_t*)g_w2)[w] = pkh(W2[k * HID + n], W2[(k + 1) * HID + n]);
        ((uint32_t*)g_w3)[w] = pkh(W3[k * HID + n], W3[(k + 1) * HID + n]);
    }
}

__device__ __forceinline__ int calc_bin(const float* __restrict__ p, int i, int j) {
    const float dx = __ldg(&p[3 * i + 0]) - __ldg(&p[3 * j + 0]);
    const float dy = __ldg(&p[3 * i + 1]) - __ldg(&p[3 * j + 1]);
    const float dz = __ldg(&p[3 * i + 2]) - __ldg(&p[3 * j + 2]);
    const float d = sqrtf((dx * dx + dy * dy) + dz * dz);
    const float step = (20.0f - 0.001f) / 21.0f;
    int bin = -1;
#pragma unroll
    for (int k = 0; k < NBINS; k++) {
        const float lo = 0.001f + (float)k * step;
        const float hi = (k == NBINS - 1) ? 1e8f : (0.001f + (float)(k + 1) * step);
        if (d > lo && d < hi) bin = k;
    }
    return bin;
}

// one layer: warp tile 32 edges x 32 channels; A via ldmatrix (fp16), B via __ldg
__device__ __forceinline__ void gemm_mma(uint32_t hbase, const uint4* __restrict__ wf,
                                         int wm, int wn, int lane, uint32_t lmoff,
                                         float (&acc)[2][4][4]) {
#pragma unroll
    for (int m = 0; m < 2; m++)
#pragma unroll
        for (int nt = 0; nt < 4; nt++)
#pragma unroll
            for (int q = 0; q < 4; q++) acc[m][nt][q] = 0.0f;
    const uint32_t a0b = hbase + (uint32_t)(wm * 32 * HPIT) + lmoff;
#pragma unroll 2
    for (int ks = 0; ks < 8; ks++) {
        const uint32_t ar = a0b + ks * 32;
        const uint4 a0 = ldmat4(ar);
        const uint4 a1 = ldmat4(ar + 16 * HPIT);
#pragma unroll
        for (int pr = 0; pr < 2; pr++) {
            const int prg = wn * 2 + pr;
            const uint4 b = __ldg(&wf[(ks * 8 + prg) * 32 + lane]);
            mma16816(acc[0][2 * pr + 0], a0, b.x, b.y);
            mma16816(acc[1][2 * pr + 0], a1, b.x, b.y);
            mma16816(acc[0][2 * pr + 1], a0, b.z, b.w);
            mma16816(acc[1][2 * pr + 1], a1, b.z, b.w);
        }
    }
}

// ---- main persistent kernel: 256 threads, 2 CTAs/SM, tile = 64 edges x 128 ch ----
__global__ void __launch_bounds__(TW, 2) k_main(
    const float* __restrict__ trans, const float* __restrict__ sctrans,
    const float* __restrict__ emask, const float* __restrict__ W1,
    const float* __restrict__ b2, const float* __restrict__ b3,
    const float* __restrict__ lng, const float* __restrict__ lnb,
    float* __restrict__ out, int N) {
    extern __shared__ char smc[];
    float* sWT  = (float*)(smc + OFF_WT);
    float* smk  = (float*)(smc + OFF_MSK);
    int* sbin1  = (int*)(smc + OFF_BIN1);
    int* sbin2  = (int*)(smc + OFF_BIN2);
    float* rsum = (float*)(smc + OFF_RSUM);
    float* rsq  = (float*)(smc + OFF_RSQ);

    const int tid = threadIdx.x, lane = tid & 31, wid = tid >> 5;
    const int wm = wid & 1, wn = wid >> 1;   // 2x4 warp grid: 32e x 32c tiles over 64x128
    const int gq = lane >> 2, tq = lane & 3;
    const uint32_t smb = smem_u32(smc);
    const uint32_t h1b = smb + OFF_H1;
    const uint32_t h2b = smb + OFF_H2;
    const uint32_t lmoff = (uint32_t)(((lane & 7) + 8 * ((lane >> 3) & 1)) * HPIT + (lane >> 4) * 16);
    const uint32_t smoff = (uint32_t)(((lane & 7) + 8 * ((lane >> 3) & 1)) * HPIT);

    for (int idx = tid; idx < 45 * HID; idx += TW) {
        const int q = idx >> 7, c = idx & 127;
        sWT[q * WTP + c] = (q < 44) ? W1[(384 + q) * HID + c] : 0.0f;
    }
    if (tid < HID) {
        ((float*)(smc + OFF_SB2))[tid] = b2[tid];
        ((float*)(smc + OFF_SB3))[tid] = b3[tid];
        ((float*)(smc + OFF_SG))[tid]  = lng[tid];
        ((float*)(smc + OFF_SBT))[tid] = lnb[tid];
    }
    __syncthreads();

    const int tpr = N / ETILE, ntiles = N * tpr;

    for (int t0 = blockIdx.x; t0 < ntiles; t0 += gridDim.x) {
        const int i = t0 / tpr;
        const int jb = (t0 - i * tpr) * ETILE;

        if (tid < ETILE) {
            const int j = jb + tid;
            const int q1 = calc_bin(trans, i, j);
            const int q2 = calc_bin(sctrans, i, j);
            sbin1[tid] = (q1 < 0 ? 44 : q1) * WTP;
            sbin2[tid] = (q2 < 0 ? 44 : 22 + q2) * WTP;
            smk[tid] = emask[i * N + j];
        }
        __syncthreads();

        // ---- phase 0: assemble h1 = relu(A+B+R+tabs), fp16 pack, edge-major store ----
        {
            const int e = 8 * wid + (lane & 7);
            const int sub = lane >> 3;
            const int j = jb + e;
            const float* ap = &g_A[i * HID];
            const float* bp = &g_B[j * HID];
            const float* rp = &g_R[(size_t)(i - j + N - 1) * HID];
            const float* t1p = &sWT[sbin1[e]];
            const float* t2p = &sWT[sbin2[e]];
#pragma unroll
            for (int cg = 0; cg < 4; cg++) {
                const int c0 = sub * 32 + cg * 8;
                float v[8];
#pragma unroll
                for (int h4 = 0; h4 < 2; h4++) {
                    const int c = c0 + 4 * h4;
                    const float4 av = *(const float4*)&ap[c];
                    const float4 bv = *(const float4*)&bp[c];
                    const float4 rv = *(const float4*)&rp[c];
                    const float4 w1v = *(const float4*)&t1p[c];
                    const float4 w2v = *(const float4*)&t2p[c];
                    v[4 * h4 + 0] = fmaxf(av.x + bv.x + rv.x + w1v.x + w2v.x, 0.0f);
                    v[4 * h4 + 1] = fmaxf(av.y + bv.y + rv.y + w1v.y + w2v.y, 0.0f);
                    v[4 * h4 + 2] = fmaxf(av.z + bv.z + rv.z + w1v.z + w2v.z, 0.0f);
                    v[4 * h4 + 3] = fmaxf(av.w + bv.w + rv.w + w1v.w + w2v.w, 0.0f);
                }
                const uint4 hv = make_uint4(pkh(v[0], v[1]), pkh(v[2], v[3]),
                                            pkh(v[4], v[5]), pkh(v[6], v[7]));
                *(uint4*)(smc + OFF_H1 + e * HPIT + c0 * 2) = hv;
            }
        }
        __syncthreads();

        float acc[2][4][4];

        // ---- layer 2 GEMM (reads H1) + epilogue (bias+relu -> H2 via stmatrix) ----
        gemm_mma(h1b, g_w2, wm, wn, lane, lmoff, acc);
#pragma unroll
        for (int m = 0; m < 2; m++) {
            const uint32_t rowb = h2b + (uint32_t)((2 * wm + m) * 16 * HPIT) + smoff;
#pragma unroll
            for (int nt = 0; nt < 4; nt++) {
                const int ntg = wn * 4 + nt;
                const int col = ntg * 8 + 2 * tq;
                const float2 bb = *(const float2*)(smc + OFF_SB2 + col * 4);
                const float v0 = fmaxf(acc[m][nt][0] + bb.x, 0.0f);
                const float v1 = fmaxf(acc[m][nt][1] + bb.y, 0.0f);
                const float v2 = fmaxf(acc[m][nt][2] + bb.x, 0.0f);
                const float v3 = fmaxf(acc[m][nt][3] + bb.y, 0.0f);
                stmat2(rowb + (uint32_t)(ntg * 16), pkh(v0, v1), pkh(v2, v3));
            }
        }
        __syncthreads();

        // ---- layer 3 GEMM (reads H2) ----
        gemm_mma(h2b, g_w3, wm, wn, lane, lmoff, acc);

        // ---- bias + LayerNorm + mask + store ----
        {
            float s[2][2] = {{0, 0}, {0, 0}}, q[2][2] = {{0, 0}, {0, 0}};
#pragma unroll
            for (int m = 0; m < 2; m++)
#pragma unroll
                for (int nt = 0; nt < 4; nt++) {
                    const int col = (wn * 4 + nt) * 8 + 2 * tq;
                    const float2 bb = *(const float2*)(smc + OFF_SB3 + col * 4);
                    acc[m][nt][0] += bb.x;
                    acc[m][nt][1] += bb.y;
                    acc[m][nt][2] += bb.x;
                    acc[m][nt][3] += bb.y;
                    s[m][0] += acc[m][nt][0] + acc[m][nt][1];
                    s[m][1] += acc[m][nt][2] + acc[m][nt][3];
                    q[m][0] += acc[m][nt][0] * acc[m][nt][0] + acc[m][nt][1] * acc[m][nt][1];
                    q[m][1] += acc[m][nt][2] * acc[m][nt][2] + acc[m][nt][3] * acc[m][nt][3];
                }
#pragma unroll
            for (int m = 0; m < 2; m++)
#pragma unroll
                for (int h = 0; h < 2; h++) {
                    s[m][h] += __shfl_xor_sync(0xffffffffu, s[m][h], 1);
                    s[m][h] += __shfl_xor_sync(0xffffffffu, s[m][h], 2);
                    q[m][h] += __shfl_xor_sync(0xffffffffu, q[m][h], 1);
                    q[m][h] += __shfl_xor_sync(0xffffffffu, q[m][h], 2);
                }
            if (tq == 0) {
#pragma unroll
                for (int m = 0; m < 2; m++)
#pragma unroll
                    for (int h = 0; h < 2; h++) {
                        const int row = (2 * wm + m) * 16 + gq + 8 * h;
                        rsum[wn * 64 + row] = s[m][h];
                        rsq[wn * 64 + row] = q[m][h];
                    }
            }
            __syncthreads();
#pragma unroll
            for (int m = 0; m < 2; m++)
#pragma unroll
                for (int h = 0; h < 2; h++) {
                    const int row = (2 * wm + m) * 16 + gq + 8 * h;
                    const float S = (rsum[row] + rsum[64 + row]) + (rsum[128 + row] + rsum[192 + row]);
                    const float Q = (rsq[row] + rsq[64 + row]) + (rsq[128 + row] + rsq[192 + row]);
                    const float mu = S * (1.0f / 128.0f);
                    const float var = Q * (1.0f / 128.0f) - mu * mu;
                    const float rstd = rsqrtf(var + 1e-5f);
                    const float msk = smk[row];
                    float* op = &out[((size_t)(i * N + jb + row)) * HID];
#pragma unroll
                    for (int nt = 0; nt < 4; nt++) {
                        const int col = (wn * 4 + nt) * 8 + 2 * tq;
                        const float2 gg = *(const float2*)(smc + OFF_SG + col * 4);
                        const float2 bt = *(const float2*)(smc + OFF_SBT + col * 4);
                        const float a = acc[m][nt][2 * h + 0];
                        const float b = acc[m][nt][2 * h + 1];
                        float2 o;
                        o.x = ((a - mu) * rstd * gg.x + bt.x) * msk;
                        o.y = ((b - mu) * rstd * gg.y + bt.y) * msk;
                        *(float2*)(op + col) = o;
                    }
                }
        }
        __syncthreads();
    }
}

// ---- launch ----
extern "C" void kernel_launch(void* const* d_in, const int* in_sizes, int n_in,
                              void* d_out, int out_size) {
    const float* nf    = (const float*)d_in[0];
    const float* trans = (const float*)d_in[1];
    const float* sct   = (const float*)d_in[2];
    const float* emask = (const float*)d_in[3];
    const float* flow  = (const float*)d_in[4];
    const float* W_n2e = (const float*)d_in[5];
    const float* b_n2e = (const float*)d_in[6];
    const float* W_rp  = (const float*)d_in[7];
    const float* b_rp  = (const float*)d_in[8];
    const float* W1    = (const float*)d_in[9];
    const float* b1    = (const float*)d_in[10];
    const float* W2    = (const float*)d_in[11];
    const float* b2    = (const float*)d_in[12];
    const float* W3    = (const float*)d_in[13];
    const float* b3    = (const float*)d_in[14];
    const float* lng   = (const float*)d_in[15];
    const float* lnb   = (const float*)d_in[16];
    float* out = (float*)d_out;

    const int N = in_sizes[4];

    k_pre2<<<3 * N - 1 + 64, 128>>>(nf, W_n2e, b_n2e, W1, b1, flow, W_rp, b_rp, W2, W3, N);

    cudaFuncSetAttribute((const void*)k_main,
                         cudaFuncAttributeMaxDynamicSharedMemorySize, SMEM_BYTES);
    k_main<<<304, TW, SMEM_BYTES>>>(trans, sct, emask, W1, b2, b3,
                                    lng, lnb, out, N);
}

// round 15
// speedup vs baseline: 2.4753x; 1.2066x over previous
#include <cuda_runtime.h>
#include <cuda_fp16.h>
#include <math.h>
#include <stdint.h>

#define HID   128
#define NODEF 256
#define NBINS 22
#define ETILE 64
#define TW    256
#define WTH_P 136            // table row pitch in halves (272B)
#define HPIT  272            // bytes per h row (256 data + 16 pad); 68 words = 4 mod 32

// ---- smem byte offsets (total 51920 -> 2 CTAs/SM) ----
#define OFF_H1   0           // 64*272 = 17408 (fp16 h1)
#define OFF_H2   17408       // 17408 (fp16 h2)
#define OFF_WTH  34816       // half[45][136] = 12240 (row 44 = zeros)
#define OFF_SB2  47056
#define OFF_SB3  47568
#define OFF_SG   48080
#define OFF_SBT  48592
#define OFF_MSK  49104       // float[64]
#define OFF_BIN1 49360       // int[64]
#define OFF_BIN2 49616       // int[64]
#define OFF_RSUM 49872       // float[4][64]
#define OFF_RSQ  50896       // float[4][64]
#define SMEM_BYTES 51920

__device__ float g_A[512 * HID];
__device__ uint4 g_Bh[512 * HID / 8];    // fp16 B rows (16B aligned)
__device__ uint4 g_Rh[1023 * HID / 8];   // fp16 R rows
// W2/W3 fp16 fragment tiles (B-operand layout), L1/L2 resident
__device__ uint4 g_w2[2048], g_w3[2048];

// ---- helpers ----
__device__ __forceinline__ uint32_t pkh(float a, float b) {  // lo half = a
    __half2 h = __floats2half2_rn(a, b);
    return *reinterpret_cast<uint32_t*>(&h);
}
__device__ __forceinline__ float2 h2f(uint32_t u) {
    return __half22float2(*reinterpret_cast<__half2*>(&u));
}
__device__ __forceinline__ void unpack8(const uint4& u, float* o) {
    float2 f;
    f = h2f(u.x); o[0] = f.x; o[1] = f.y;
    f = h2f(u.y); o[2] = f.x; o[3] = f.y;
    f = h2f(u.z); o[4] = f.x; o[5] = f.y;
    f = h2f(u.w); o[6] = f.x; o[7] = f.y;
}
__device__ __forceinline__ void mma16816(float (&d)[4], const uint4& a, uint32_t b0, uint32_t b1) {
    asm volatile("mma.sync.aligned.m16n8k16.row.col.f32.f16.f16.f32 "
                 "{%0,%1,%2,%3}, {%4,%5,%6,%7}, {%8,%9}, {%0,%1,%2,%3};"
                 : "+f"(d[0]), "+f"(d[1]), "+f"(d[2]), "+f"(d[3])
                 : "r"(a.x), "r"(a.y), "r"(a.z), "r"(a.w), "r"(b0), "r"(b1));
}
__device__ __forceinline__ uint4 ldmat4(uint32_t a) {
    uint4 r;
    asm volatile("ldmatrix.sync.aligned.m8n8.x4.shared.b16 {%0,%1,%2,%3}, [%4];"
                 : "=r"(r.x), "=r"(r.y), "=r"(r.z), "=r"(r.w) : "r"(a));
    return r;
}
__device__ __forceinline__ void stmat2(uint32_t a, uint32_t r0, uint32_t r1) {
    asm volatile("stmatrix.sync.aligned.m8n8.x2.shared.b16 [%0], {%1,%2};"
                 :: "r"(a), "r"(r0), "r"(r1));
}
__device__ __forceinline__ uint32_t smem_u32(const void* p) {
    uint32_t a;
    asm("{ .reg .u64 t; cvta.to.shared.u64 t, %1; cvt.u32.u64 %0, t; }" : "=r"(a) : "l"(p));
    return a;
}

// ---- merged precompute: [0,N) A/B rows; [N,3N-1) R rows; [3N-1, +64) W frags ----
__global__ void k_pre2(const float* __restrict__ nf, const float* __restrict__ Wn,
                       const float* __restrict__ bn, const float* __restrict__ W1,
                       const float* __restrict__ b1, const float* __restrict__ flow,
                       const float* __restrict__ Wrp, const float* __restrict__ brp,
                       const float* __restrict__ W2, const float* __restrict__ W3,
                       int N) {
    const int c = threadIdx.x;
    if ((int)blockIdx.x < N) {
        __shared__ float row[NODEF];
        __shared__ float n2e[HID];
        const int i = blockIdx.x;
        row[c] = nf[i * NODEF + c];
        row[c + 128] = nf[i * NODEF + 128 + c];
        __syncthreads();
        float s0 = bn[c], s1 = 0.0f;
#pragma unroll 4
        for (int k = 0; k < NODEF; k += 2) {
            s0 += row[k] * Wn[k * HID + c];
            s1 += row[k + 1] * Wn[(k + 1) * HID + c];
        }
        n2e[c] = s0 + s1;
        __syncthreads();
        const float fi = flow[i];
        float a0 = b1[c] + fi * W1[428 * HID + c], a1 = 0.0f;
        float b0 = fi * W1[429 * HID + c], bb1 = 0.0f;
#pragma unroll 4
        for (int k = 0; k < HID; k += 2) {
            const float v0 = n2e[k], v1 = n2e[k + 1];
            a0 += v0 * W1[k * HID + c];
            a1 += v1 * W1[(k + 1) * HID + c];
            b0 += v0 * W1[(128 + k) * HID + c];
            bb1 += v1 * W1[(128 + k + 1) * HID + c];
        }
        g_A[i * HID + c] = a0 + a1;
        ((__half*)g_Bh)[i * HID + c] = __float2half_rn(b0 + bb1);
    } else if ((int)blockIdx.x < 3 * N - 1) {
        __shared__ float emb[HID];
        __shared__ float rp[HID];
        const int bi = blockIdx.x - N;
        const float d = (float)(bi - (N - 1));
        if (c < 64) {
            float den = (float)pow(2056.0, (double)c * (1.0 / 64.0));
            float ang = (d * 3.14159274101257324f) / den;
            emb[c] = (float)sin((double)ang);
            emb[c + 64] = (float)cos((double)ang);
        }
        __syncthreads();
        float s0 = brp[c], s1 = 0.0f;
#pragma unroll 4
        for (int k = 0; k < HID; k += 2) {
            s0 += emb[k] * Wrp[k * HID + c];
            s1 += emb[k + 1] * Wrp[(k + 1) * HID + c];
        }
        rp[c] = s0 + s1;
        __syncthreads();
        float r0 = 0.0f, r1 = 0.0f;
#pragma unroll 4
        for (int k = 0; k < HID; k += 2) {
            r0 += rp[k] * W1[(256 + k) * HID + c];
            r1 += rp[k + 1] * W1[(256 + k + 1) * HID + c];
        }
        ((__half*)g_Rh)[bi * HID + c] = __float2half_rn(r0 + r1);
    } else {
        // W fragment prep: idx in [0, 8192)
        const int idx = (blockIdx.x - (3 * N - 1)) * 128 + c;
        const int n = idx >> 6, k = (idx & 63) * 2;
        const int ntg = n >> 3, gg = n & 7;
        const int t = (k >> 1) & 3, ks = k >> 4, r = (k >> 3) & 1;
        const int w = ((((ks * 8 + (ntg >> 1)) * 32 + 4 * gg + t) << 2) + ((ntg & 1) << 1) + r);
        ((uint32_t*)g_w2)[w] = pkh(W2[k * HID + n], W2[(k + 1) * HID + n]);
        ((uint32_t*)g_w3)[w] = pkh(W3[k * HID + n], W3[(k + 1) * HID + n]);
    }
}

__device__ __forceinline__ int calc_bin(const float* __restrict__ p, int i, int j) {
    const float dx = __ldg(&p[3 * i + 0]) - __ldg(&p[3 * j + 0]);
    const float dy = __ldg(&p[3 * i + 1]) - __ldg(&p[3 * j + 1]);
    const float dz = __ldg(&p[3 * i + 2]) - __ldg(&p[3 * j + 2]);
    const float d = sqrtf((dx * dx + dy * dy) + dz * dz);
    const float step = (20.0f - 0.001f) / 21.0f;
    int bin = -1;
#pragma unroll
    for (int k = 0; k < NBINS; k++) {
        const float lo = 0.001f + (float)k * step;
        const float hi = (k == NBINS - 1) ? 1e8f : (0.001f + (float)(k + 1) * step);
        if (d > lo && d < hi) bin = k;
    }
    return bin;
}

// one layer: warp tile 32 edges x 32 channels; A via ldmatrix (fp16), B via __ldg
__device__ __forceinline__ void gemm_mma(uint32_t hbase, const uint4* __restrict__ wf,
                                         int wm, int wn, int lane, uint32_t lmoff,
                                         float (&acc)[2][4][4]) {
#pragma unroll
    for (int m = 0; m < 2; m++)
#pragma unroll
        for (int nt = 0; nt < 4; nt++)
#pragma unroll
            for (int q = 0; q < 4; q++) acc[m][nt][q] = 0.0f;
    const uint32_t a0b = hbase + (uint32_t)(wm * 32 * HPIT) + lmoff;
#pragma unroll 2
    for (int ks = 0; ks < 8; ks++) {
        const uint32_t ar = a0b + ks * 32;
        const uint4 a0 = ldmat4(ar);
        const uint4 a1 = ldmat4(ar + 16 * HPIT);
#pragma unroll
        for (int pr = 0; pr < 2; pr++) {
            const int prg = wn * 2 + pr;
            const uint4 b = __ldg(&wf[(ks * 8 + prg) * 32 + lane]);
            mma16816(acc[0][2 * pr + 0], a0, b.x, b.y);
            mma16816(acc[1][2 * pr + 0], a1, b.x, b.y);
            mma16816(acc[0][2 * pr + 1], a0, b.z, b.w);
            mma16816(acc[1][2 * pr + 1], a1, b.z, b.w);
        }
    }
}

// ---- main persistent kernel: 256 threads, 2 CTAs/SM, tile = 64 edges x 128 ch ----
__global__ void __launch_bounds__(TW, 2) k_main(
    const float* __restrict__ trans, const float* __restrict__ sctrans,
    const float* __restrict__ emask, const float* __restrict__ W1,
    const float* __restrict__ b2, const float* __restrict__ b3,
    const float* __restrict__ lng, const float* __restrict__ lnb,
    float* __restrict__ out, int N) {
    extern __shared__ char smc[];
    __half* sWTh = (__half*)(smc + OFF_WTH);
    float* smk  = (float*)(smc + OFF_MSK);
    int* sbin1  = (int*)(smc + OFF_BIN1);
    int* sbin2  = (int*)(smc + OFF_BIN2);
    float* rsum = (float*)(smc + OFF_RSUM);
    float* rsq  = (float*)(smc + OFF_RSQ);

    const int tid = threadIdx.x, lane = tid & 31, wid = tid >> 5;
    const int wm = wid & 1, wn = wid >> 1;   // 2x4 warp grid: 32e x 32c tiles over 64x128
    const int gq = lane >> 2, tq = lane & 3;
    const uint32_t smb = smem_u32(smc);
    const uint32_t h1b = smb + OFF_H1;
    const uint32_t h2b = smb + OFF_H2;
    const uint32_t lmoff = (uint32_t)(((lane & 7) + 8 * ((lane >> 3) & 1)) * HPIT + (lane >> 4) * 16);
    const uint32_t smoff = (uint32_t)(((lane & 7) + 8 * ((lane >> 3) & 1)) * HPIT);

    for (int idx = tid; idx < 45 * HID; idx += TW) {
        const int q = idx >> 7, c = idx & 127;
        sWTh[q * WTH_P + c] = __float2half_rn((q < 44) ? W1[(384 + q) * HID + c] : 0.0f);
    }
    if (tid < HID) {
        ((float*)(smc + OFF_SB2))[tid] = b2[tid];
        ((float*)(smc + OFF_SB3))[tid] = b3[tid];
        ((float*)(smc + OFF_SG))[tid]  = lng[tid];
        ((float*)(smc + OFF_SBT))[tid] = lnb[tid];
    }
    __syncthreads();

    const int tpr = N / ETILE, ntiles = N * tpr;

    for (int t0 = blockIdx.x; t0 < ntiles; t0 += gridDim.x) {
        const int i = t0 / tpr;
        const int jb = (t0 - i * tpr) * ETILE;

        if (tid < ETILE) {
            const int j = jb + tid;
            const int q1 = calc_bin(trans, i, j);
            const int q2 = calc_bin(sctrans, i, j);
            sbin1[tid] = (q1 < 0 ? 44 : q1) * WTH_P;
            sbin2[tid] = (q2 < 0 ? 44 : 22 + q2) * WTH_P;
            smk[tid] = emask[i * N + j];
        }
        __syncthreads();

        // ---- phase 0: h1 = relu(A + B + R + T1 + T2) (fp16 terms, fp32 sum) ----
        {
            const int e = 8 * wid + (lane & 7);
            const int sub = lane >> 3;
            const int j = jb + e;
            const float* ap = &g_A[i * HID];
            const __half* bph = (const __half*)g_Bh + j * HID;
            const __half* rph = (const __half*)g_Rh + (size_t)(i - j + N - 1) * HID;
            const __half* t1p = sWTh + sbin1[e];
            const __half* t2p = sWTh + sbin2[e];
#pragma unroll
            for (int cg = 0; cg < 4; cg++) {
                const int c0 = sub * 32 + cg * 8;
                const float4 av0 = *(const float4*)&ap[c0];
                const float4 av1 = *(const float4*)&ap[c0 + 4];
                float vb[8], vr[8], v1t[8], v2t[8];
                unpack8(*(const uint4*)(bph + c0), vb);
                unpack8(*(const uint4*)(rph + c0), vr);
                unpack8(*(const uint4*)(t1p + c0), v1t);
                unpack8(*(const uint4*)(t2p + c0), v2t);
                float v[8];
                v[0] = fmaxf(av0.x + vb[0] + vr[0] + v1t[0] + v2t[0], 0.0f);
                v[1] = fmaxf(av0.y + vb[1] + vr[1] + v1t[1] + v2t[1], 0.0f);
                v[2] = fmaxf(av0.z + vb[2] + vr[2] + v1t[2] + v2t[2], 0.0f);
                v[3] = fmaxf(av0.w + vb[3] + vr[3] + v1t[3] + v2t[3], 0.0f);
                v[4] = fmaxf(av1.x + vb[4] + vr[4] + v1t[4] + v2t[4], 0.0f);
                v[5] = fmaxf(av1.y + vb[5] + vr[5] + v1t[5] + v2t[5], 0.0f);
                v[6] = fmaxf(av1.z + vb[6] + vr[6] + v1t[6] + v2t[6], 0.0f);
                v[7] = fmaxf(av1.w + vb[7] + vr[7] + v1t[7] + v2t[7], 0.0f);
                const uint4 hv = make_uint4(pkh(v[0], v[1]), pkh(v[2], v[3]),
                                            pkh(v[4], v[5]), pkh(v[6], v[7]));
                *(uint4*)(smc + OFF_H1 + e * HPIT + c0 * 2) = hv;
            }
        }
        __syncthreads();

        float acc[2][4][4];

        // ---- layer 2 GEMM (reads H1) + epilogue (bias+relu -> H2 via stmatrix) ----
        gemm_mma(h1b, g_w2, wm, wn, lane, lmoff, acc);
#pragma unroll
        for (int m = 0; m < 2; m++) {
            const uint32_t rowb = h2b + (uint32_t)((2 * wm + m) * 16 * HPIT) + smoff;
#pragma unroll
            for (int nt = 0; nt < 4; nt++) {
                const int ntg = wn * 4 + nt;
                const int col = ntg * 8 + 2 * tq;
                const float2 bb = *(const float2*)(smc + OFF_SB2 + col * 4);
                const float v0 = fmaxf(acc[m][nt][0] + bb.x, 0.0f);
                const float v1 = fmaxf(acc[m][nt][1] + bb.y, 0.0f);
                const float v2 = fmaxf(acc[m][nt][2] + bb.x, 0.0f);
                const float v3 = fmaxf(acc[m][nt][3] + bb.y, 0.0f);
                stmat2(rowb + (uint32_t)(ntg * 16), pkh(v0, v1), pkh(v2, v3));
            }
        }
        __syncthreads();

        // ---- layer 3 GEMM (reads H2) ----
        gemm_mma(h2b, g_w3, wm, wn, lane, lmoff, acc);

        // ---- bias + LayerNorm + mask + store ----
        {
            float s[2][2] = {{0, 0}, {0, 0}}, q[2][2] = {{0, 0}, {0, 0}};
#pragma unroll
            for (int m = 0; m < 2; m++)
#pragma unroll
                for (int nt = 0; nt < 4; nt++) {
                    const int col = (wn * 4 + nt) * 8 + 2 * tq;
                    const float2 bb = *(const float2*)(smc + OFF_SB3 + col * 4);
                    acc[m][nt][0] += bb.x;
                    acc[m][nt][1] += bb.y;
                    acc[m][nt][2] += bb.x;
                    acc[m][nt][3] += bb.y;
                    s[m][0] += acc[m][nt][0] + acc[m][nt][1];
                    s[m][1] += acc[m][nt][2] + acc[m][nt][3];
                    q[m][0] += acc[m][nt][0] * acc[m][nt][0] + acc[m][nt][1] * acc[m][nt][1];
                    q[m][1] += acc[m][nt][2] * acc[m][nt][2] + acc[m][nt][3] * acc[m][nt][3];
                }
#pragma unroll
            for (int m = 0; m < 2; m++)
#pragma unroll
                for (int h = 0; h < 2; h++) {
                    s[m][h] += __shfl_xor_sync(0xffffffffu, s[m][h], 1);
                    s[m][h] += __shfl_xor_sync(0xffffffffu, s[m][h], 2);
                    q[m][h] += __shfl_xor_sync(0xffffffffu, q[m][h], 1);
                    q[m][h] += __shfl_xor_sync(0xffffffffu, q[m][h], 2);
                }
            if (tq == 0) {
#pragma unroll
                for (int m = 0; m < 2; m++)
#pragma unroll
                    for (int h = 0; h < 2; h++) {
                        const int row = (2 * wm + m) * 16 + gq + 8 * h;
                        rsum[wn * 64 + row] = s[m][h];
                        rsq[wn * 64 + row] = q[m][h];
                    }
            }
            __syncthreads();
#pragma unroll
            for (int m = 0; m < 2; m++)
#pragma unroll
                for (int h = 0; h < 2; h++) {
                    const int row = (2 * wm + m) * 16 + gq + 8 * h;
                    const float S = (rsum[row] + rsum[64 + row]) + (rsum[128 + row] + rsum[192 + row]);
                    const float Q = (rsq[row] + rsq[64 + row]) + (rsq[128 + row] + rsq[192 + row]);
                    const float mu = S * (1.0f / 128.0f);
                    const float var = Q * (1.0f / 128.0f) - mu * mu;
                    const float rstd = rsqrtf(var + 1e-5f);
                    const float msk = smk[row];
                    float* op = &out[((size_t)(i * N + jb + row)) * HID];
#pragma unroll
                    for (int nt = 0; nt < 4; nt++) {
                        const int col = (wn * 4 + nt) * 8 + 2 * tq;
                        const float2 gg = *(const float2*)(smc + OFF_SG + col * 4);
                        const float2 bt = *(const float2*)(smc + OFF_SBT + col * 4);
                        const float a = acc[m][nt][2 * h + 0];
                        const float b = acc[m][nt][2 * h + 1];
                        float2 o;
                        o.x = ((a - mu) * rstd * gg.x + bt.x) * msk;
                        o.y = ((b - mu) * rstd * gg.y + bt.y) * msk;
                        *(float2*)(op + col) = o;
                    }
                }
        }
        __syncthreads();
    }
}

// ---- launch ----
extern "C" void kernel_launch(void* const* d_in, const int* in_sizes, int n_in,
                              void* d_out, int out_size) {
    const float* nf    = (const float*)d_in[0];
    const float* trans = (const float*)d_in[1];
    const float* sct   = (const float*)d_in[2];
    const float* emask = (const float*)d_in[3];
    const float* flow  = (const float*)d_in[4];
    const float* W_n2e = (const float*)d_in[5];
    const float* b_n2e = (const float*)d_in[6];
    const float* W_rp  = (const float*)d_in[7];
    const float* b_rp  = (const float*)d_in[8];
    const float* W1    = (const float*)d_in[9];
    const float* b1    = (const float*)d_in[10];
    const float* W2    = (const float*)d_in[11];
    const float* b2    = (const float*)d_in[12];
    const float* W3    = (const float*)d_in[13];
    const float* b3    = (const float*)d_in[14];
    const float* lng   = (const float*)d_in[15];
    const float* lnb   = (const float*)d_in[16];
    float* out = (float*)d_out;

    const int N = in_sizes[4];

    k_pre2<<<3 * N - 1 + 64, 128>>>(nf, W_n2e, b_n2e, W1, b1, flow, W_rp, b_rp, W2, W3, N);

    cudaFuncSetAttribute((const void*)k_main,
                         cudaFuncAttributeMaxDynamicSharedMemorySize, SMEM_BYTES);
    k_main<<<304, TW, SMEM_BYTES>>>(trans, sct, emask, W1, b2, b3,
                                    lng, lnb, out, N);
}

// round 16
// speedup vs baseline: 2.4996x; 1.0098x over previous
#include <cuda_runtime.h>
#include <cuda_fp16.h>
#include <math.h>
#include <stdint.h>

#define HID   128
#define NODEF 256
#define NBINS 22
#define ETILE 64
#define TW    256
#define WTH_P 136            // table row pitch in halves (272B)
#define HPIT  272            // bytes per h row (256 data + 16 pad); 68 words = 4 mod 32

// ---- smem byte offsets (total 51920 -> 2 CTAs/SM) ----
#define OFF_H1   0           // 64*272 = 17408 (fp16 h1)
#define OFF_H2   17408       // 17408 (fp16 h2)
#define OFF_WTH  34816       // half[45][136] = 12240 (row 44 = zeros)
#define OFF_SB2  47056
#define OFF_SB3  47568
#define OFF_SG   48080
#define OFF_SBT  48592
#define OFF_MSK  49104       // float[64]
#define OFF_BIN1 49360       // int[64]
#define OFF_BIN2 49616       // int[64]
#define OFF_RSUM 49872       // float[4][64]
#define OFF_RSQ  50896       // float[4][64]
#define SMEM_BYTES 51920

__device__ uint4 g_Ah[512 * HID / 8];    // fp16 A rows
__device__ uint4 g_Bh[512 * HID / 8];    // fp16 B rows
__device__ uint4 g_Rh[1023 * HID / 8];   // fp16 R rows
// W2/W3 fp16 fragment tiles (B-operand layout), L1/L2 resident
__device__ uint4 g_w2[2048], g_w3[2048];

// ---- helpers ----
__device__ __forceinline__ uint32_t pkh(float a, float b) {  // lo half = a
    __half2 h = __floats2half2_rn(a, b);
    return *reinterpret_cast<uint32_t*>(&h);
}
__device__ __forceinline__ uint32_t hadd2(uint32_t a, uint32_t b) {
    uint32_t d;
    asm("add.f16x2 %0, %1, %2;" : "=r"(d) : "r"(a), "r"(b));
    return d;
}
__device__ __forceinline__ uint32_t hmax2z(uint32_t a) {
    uint32_t d;
    asm("max.f16x2 %0, %1, %2;" : "=r"(d) : "r"(a), "r"(0u));
    return d;
}
__device__ __forceinline__ void mma16816(float (&d)[4], const uint4& a, uint32_t b0, uint32_t b1) {
    asm volatile("mma.sync.aligned.m16n8k16.row.col.f32.f16.f16.f32 "
                 "{%0,%1,%2,%3}, {%4,%5,%6,%7}, {%8,%9}, {%0,%1,%2,%3};"
                 : "+f"(d[0]), "+f"(d[1]), "+f"(d[2]), "+f"(d[3])
                 : "r"(a.x), "r"(a.y), "r"(a.z), "r"(a.w), "r"(b0), "r"(b1));
}
__device__ __forceinline__ uint4 ldmat4(uint32_t a) {
    uint4 r;
    asm volatile("ldmatrix.sync.aligned.m8n8.x4.shared.b16 {%0,%1,%2,%3}, [%4];"
                 : "=r"(r.x), "=r"(r.y), "=r"(r.z), "=r"(r.w) : "r"(a));
    return r;
}
__device__ __forceinline__ void stmat2(uint32_t a, uint32_t r0, uint32_t r1) {
    asm volatile("stmatrix.sync.aligned.m8n8.x2.shared.b16 [%0], {%1,%2};"
                 :: "r"(a), "r"(r0), "r"(r1));
}
__device__ __forceinline__ uint32_t smem_u32(const void* p) {
    uint32_t a;
    asm("{ .reg .u64 t; cvta.to.shared.u64 t, %1; cvt.u32.u64 %0, t; }" : "=r"(a) : "l"(p));
    return a;
}

// ---- merged precompute: [0,N) A/B rows; [N,3N-1) R rows; [3N-1, +64) W frags ----
__global__ void k_pre2(const float* __restrict__ nf, const float* __restrict__ Wn,
                       const float* __restrict__ bn, const float* __restrict__ W1,
                       const float* __restrict__ b1, const float* __restrict__ flow,
                       const float* __restrict__ Wrp, const float* __restrict__ brp,
                       const float* __restrict__ W2, const float* __restrict__ W3,
                       int N) {
    const int c = threadIdx.x;
    if ((int)blockIdx.x < N) {
        __shared__ float row[NODEF];
        __shared__ float n2e[HID];
        const int i = blockIdx.x;
        row[c] = nf[i * NODEF + c];
        row[c + 128] = nf[i * NODEF + 128 + c];
        __syncthreads();
        float s0 = bn[c], s1 = 0.0f;
#pragma unroll 4
        for (int k = 0; k < NODEF; k += 2) {
            s0 += row[k] * Wn[k * HID + c];
            s1 += row[k + 1] * Wn[(k + 1) * HID + c];
        }
        n2e[c] = s0 + s1;
        __syncthreads();
        const float fi = flow[i];
        float a0 = b1[c] + fi * W1[428 * HID + c], a1 = 0.0f;
        float b0 = fi * W1[429 * HID + c], bb1 = 0.0f;
#pragma unroll 4
        for (int k = 0; k < HID; k += 2) {
            const float v0 = n2e[k], v1 = n2e[k + 1];
            a0 += v0 * W1[k * HID + c];
            a1 += v1 * W1[(k + 1) * HID + c];
            b0 += v0 * W1[(128 + k) * HID + c];
            bb1 += v1 * W1[(128 + k + 1) * HID + c];
        }
        ((__half*)g_Ah)[i * HID + c] = __float2half_rn(a0 + a1);
        ((__half*)g_Bh)[i * HID + c] = __float2half_rn(b0 + bb1);
    } else if ((int)blockIdx.x < 3 * N - 1) {
        __shared__ float emb[HID];
        __shared__ float rp[HID];
        const int bi = blockIdx.x - N;
        const float d = (float)(bi - (N - 1));
        if (c < 64) {
            float den = (float)pow(2056.0, (double)c * (1.0 / 64.0));
            float ang = (d * 3.14159274101257324f) / den;
            emb[c] = (float)sin((double)ang);
            emb[c + 64] = (float)cos((double)ang);
        }
        __syncthreads();
        float s0 = brp[c], s1 = 0.0f;
#pragma unroll 4
        for (int k = 0; k < HID; k += 2) {
            s0 += emb[k] * Wrp[k * HID + c];
            s1 += emb[k + 1] * Wrp[(k + 1) * HID + c];
        }
        rp[c] = s0 + s1;
        __syncthreads();
        float r0 = 0.0f, r1 = 0.0f;
#pragma unroll 4
        for (int k = 0; k < HID; k += 2) {
            r0 += rp[k] * W1[(256 + k) * HID + c];
            r1 += rp[k + 1] * W1[(256 + k + 1) * HID + c];
        }
        ((__half*)g_Rh)[bi * HID + c] = __float2half_rn(r0 + r1);
    } else {
        // W fragment prep: idx in [0, 8192)
        const int idx = (blockIdx.x - (3 * N - 1)) * 128 + c;
        const int n = idx >> 6, k = (idx & 63) * 2;
        const int ntg = n >> 3, gg = n & 7;
        const int t = (k >> 1) & 3, ks = k >> 4, r = (k >> 3) & 1;
        const int w = ((((ks * 8 + (ntg >> 1)) * 32 + 4 * gg + t) << 2) + ((ntg & 1) << 1) + r);
        ((uint32_t*)g_w2)[w] = pkh(W2[k * HID + n], W2[(k + 1) * HID + n]);
        ((uint32_t*)g_w3)[w] = pkh(W3[k * HID + n], W3[(k + 1) * HID + n]);
    }
}

__device__ __forceinline__ int calc_bin(const float* __restrict__ p, int i, int j) {
    const float dx = __ldg(&p[3 * i + 0]) - __ldg(&p[3 * j + 0]);
    const float dy = __ldg(&p[3 * i + 1]) - __ldg(&p[3 * j + 1]);
    const float dz = __ldg(&p[3 * i + 2]) - __ldg(&p[3 * j + 2]);
    const float d = sqrtf((dx * dx + dy * dy) + dz * dz);
    const float step = (20.0f - 0.001f) / 21.0f;
    int bin = -1;
#pragma unroll
    for (int k = 0; k < NBINS; k++) {
        const float lo = 0.001f + (float)k * step;
        const float hi = (k == NBINS - 1) ? 1e8f : (0.001f + (float)(k + 1) * step);
        if (d > lo && d < hi) bin = k;
    }
    return bin;
}

// one layer: warp tile 32 edges x 32 channels; A via ldmatrix (fp16), B via __ldg
__device__ __forceinline__ void gemm_mma(uint32_t hbase, const uint4* __restrict__ wf,
                                         int wm, int wn, int lane, uint32_t lmoff,
                                         float (&acc)[2][4][4]) {
#pragma unroll
    for (int m = 0; m < 2; m++)
#pragma unroll
        for (int nt = 0; nt < 4; nt++)
#pragma unroll
            for (int q = 0; q < 4; q++) acc[m][nt][q] = 0.0f;
    const uint32_t a0b = hbase + (uint32_t)(wm * 32 * HPIT) + lmoff;
#pragma unroll 2
    for (int ks = 0; ks < 8; ks++) {
        const uint32_t ar = a0b + ks * 32;
        const uint4 a0 = ldmat4(ar);
        const uint4 a1 = ldmat4(ar + 16 * HPIT);
#pragma unroll
        for (int pr = 0; pr < 2; pr++) {
            const int prg = wn * 2 + pr;
            const uint4 b = __ldg(&wf[(ks * 8 + prg) * 32 + lane]);
            mma16816(acc[0][2 * pr + 0], a0, b.x, b.y);
            mma16816(acc[1][2 * pr + 0], a1, b.x, b.y);
            mma16816(acc[0][2 * pr + 1], a0, b.z, b.w);
            mma16816(acc[1][2 * pr + 1], a1, b.z, b.w);
        }
    }
}

// ---- main persistent kernel: 256 threads, 2 CTAs/SM, tile = 64 edges x 128 ch ----
__global__ void __launch_bounds__(TW, 2) k_main(
    const float* __restrict__ trans, const float* __restrict__ sctrans,
    const float* __restrict__ emask, const float* __restrict__ W1,
    const float* __restrict__ b2, const float* __restrict__ b3,
    const float* __restrict__ lng, const float* __restrict__ lnb,
    float* __restrict__ out, int N) {
    extern __shared__ char smc[];
    __half* sWTh = (__half*)(smc + OFF_WTH);
    float* smk  = (float*)(smc + OFF_MSK);
    int* sbin1  = (int*)(smc + OFF_BIN1);
    int* sbin2  = (int*)(smc + OFF_BIN2);
    float* rsum = (float*)(smc + OFF_RSUM);
    float* rsq  = (float*)(smc + OFF_RSQ);

    const int tid = threadIdx.x, lane = tid & 31, wid = tid >> 5;
    const int wm = wid & 1, wn = wid >> 1;   // 2x4 warp grid: 32e x 32c tiles over 64x128
    const int gq = lane >> 2, tq = lane & 3;
    const uint32_t smb = smem_u32(smc);
    const uint32_t h1b = smb + OFF_H1;
    const uint32_t h2b = smb + OFF_H2;
    const uint32_t lmoff = (uint32_t)(((lane & 7) + 8 * ((lane >> 3) & 1)) * HPIT + (lane >> 4) * 16);
    const uint32_t smoff = (uint32_t)(((lane & 7) + 8 * ((lane >> 3) & 1)) * HPIT);

    for (int idx = tid; idx < 45 * HID; idx += TW) {
        const int q = idx >> 7, c = idx & 127;
        sWTh[q * WTH_P + c] = __float2half_rn((q < 44) ? W1[(384 + q) * HID + c] : 0.0f);
    }
    if (tid < HID) {
        ((float*)(smc + OFF_SB2))[tid] = b2[tid];
        ((float*)(smc + OFF_SB3))[tid] = b3[tid];
        ((float*)(smc + OFF_SG))[tid]  = lng[tid];
        ((float*)(smc + OFF_SBT))[tid] = lnb[tid];
    }
    __syncthreads();

    const int tpr = N / ETILE, ntiles = N * tpr;

    for (int t0 = blockIdx.x; t0 < ntiles; t0 += gridDim.x) {
        const int i = t0 / tpr;
        const int jb = (t0 - i * tpr) * ETILE;

        if (tid < ETILE) {
            const int j = jb + tid;
            const int q1 = calc_bin(trans, i, j);
            const int q2 = calc_bin(sctrans, i, j);
            sbin1[tid] = (q1 < 0 ? 44 : q1) * WTH_P;
            sbin2[tid] = (q2 < 0 ? 44 : 22 + q2) * WTH_P;
            smk[tid] = emask[i * N + j];
        }
        __syncthreads();

        // ---- phase 0: h1 = relu(A + B + R + T1 + T2), all packed fp16 ----
        {
            const int e = 8 * wid + (lane & 7);
            const int sub = lane >> 3;
            const int j = jb + e;
            const __half* aph = (const __half*)g_Ah + i * HID;
            const __half* bph = (const __half*)g_Bh + j * HID;
            const __half* rph = (const __half*)g_Rh + (size_t)(i - j + N - 1) * HID;
            const __half* t1p = sWTh + sbin1[e];
            const __half* t2p = sWTh + sbin2[e];
#pragma unroll
            for (int cg = 0; cg < 4; cg++) {
                const int c0 = sub * 32 + cg * 8;
                const uint4 a  = *(const uint4*)(aph + c0);
                const uint4 b  = *(const uint4*)(bph + c0);
                const uint4 r  = *(const uint4*)(rph + c0);
                const uint4 t1 = *(const uint4*)(t1p + c0);
                const uint4 t2 = *(const uint4*)(t2p + c0);
                uint4 o;
                o.x = hmax2z(hadd2(hadd2(a.x, b.x), hadd2(hadd2(t1.x, t2.x), r.x)));
                o.y = hmax2z(hadd2(hadd2(a.y, b.y), hadd2(hadd2(t1.y, t2.y), r.y)));
                o.z = hmax2z(hadd2(hadd2(a.z, b.z), hadd2(hadd2(t1.z, t2.z), r.z)));
                o.w = hmax2z(hadd2(hadd2(a.w, b.w), hadd2(hadd2(t1.w, t2.w), r.w)));
                *(uint4*)(smc + OFF_H1 + e * HPIT + c0 * 2) = o;
            }
        }
        __syncthreads();

        float acc[2][4][4];

        // ---- layer 2 GEMM (reads H1) + epilogue (bias+relu -> H2 via stmatrix) ----
        gemm_mma(h1b, g_w2, wm, wn, lane, lmoff, acc);
#pragma unroll
        for (int m = 0; m < 2; m++) {
            const uint32_t rowb = h2b + (uint32_t)((2 * wm + m) * 16 * HPIT) + smoff;
#pragma unroll
            for (int nt = 0; nt < 4; nt++) {
                const int ntg = wn * 4 + nt;
                const int col = ntg * 8 + 2 * tq;
                const float2 bb = *(const float2*)(smc + OFF_SB2 + col * 4);
                const float v0 = fmaxf(acc[m][nt][0] + bb.x, 0.0f);
                const float v1 = fmaxf(acc[m][nt][1] + bb.y, 0.0f);
                const float v2 = fmaxf(acc[m][nt][2] + bb.x, 0.0f);
                const float v3 = fmaxf(acc[m][nt][3] + bb.y, 0.0f);
                stmat2(rowb + (uint32_t)(ntg * 16), pkh(v0, v1), pkh(v2, v3));
            }
        }
        __syncthreads();

        // ---- layer 3 GEMM (reads H2) ----
        gemm_mma(h2b, g_w3, wm, wn, lane, lmoff, acc);

        // ---- bias + LayerNorm + mask + store ----
        {
            float s[2][2] = {{0, 0}, {0, 0}}, q[2][2] = {{0, 0}, {0, 0}};
#pragma unroll
            for (int m = 0; m < 2; m++)
#pragma unroll
                for (int nt = 0; nt < 4; nt++) {
                    const int col = (wn * 4 + nt) * 8 + 2 * tq;
                    const float2 bb = *(const float2*)(smc + OFF_SB3 + col * 4);
                    acc[m][nt][0] += bb.x;
                    acc[m][nt][1] += bb.y;
                    acc[m][nt][2] += bb.x;
                    acc[m][nt][3] += bb.y;
                    s[m][0] += acc[m][nt][0] + acc[m][nt][1];
                    s[m][1] += acc[m][nt][2] + acc[m][nt][3];
                    q[m][0] += acc[m][nt][0] * acc[m][nt][0] + acc[m][nt][1] * acc[m][nt][1];
                    q[m][1] += acc[m][nt][2] * acc[m][nt][2] + acc[m][nt][3] * acc[m][nt][3];
                }
#pragma unroll
            for (int m = 0; m < 2; m++)
#pragma unroll
                for (int h = 0; h < 2; h++) {
                    s[m][h] += __shfl_xor_sync(0xffffffffu, s[m][h], 1);
                    s[m][h] += __shfl_xor_sync(0xffffffffu, s[m][h], 2);
                    q[m][h] += __shfl_xor_sync(0xffffffffu, q[m][h], 1);
                    q[m][h] += __shfl_xor_sync(0xffffffffu, q[m][h], 2);
                }
            if (tq == 0) {
#pragma unroll
                for (int m = 0; m < 2; m++)
#pragma unroll
                    for (int h = 0; h < 2; h++) {
                        const int row = (2 * wm + m) * 16 + gq + 8 * h;
                        rsum[wn * 64 + row] = s[m][h];
                        rsq[wn * 64 + row] = q[m][h];
                    }
            }
            __syncthreads();
#pragma unroll
            for (int m = 0; m < 2; m++)
#pragma unroll
                for (int h = 0; h < 2; h++) {
                    const int row = (2 * wm + m) * 16 + gq + 8 * h;
                    const float S = (rsum[row] + rsum[64 + row]) + (rsum[128 + row] + rsum[192 + row]);
                    const float Q = (rsq[row] + rsq[64 + row]) + (rsq[128 + row] + rsq[192 + row]);
                    const float mu = S * (1.0f / 128.0f);
                    const float var = Q * (1.0f / 128.0f) - mu * mu;
                    const float rstd = rsqrtf(var + 1e-5f);
                    const float msk = smk[row];
                    float* op = &out[((size_t)(i * N + jb + row)) * HID];
#pragma unroll
                    for (int nt = 0; nt < 4; nt++) {
                        const int col = (wn * 4 + nt) * 8 + 2 * tq;
                        const float2 gg = *(const float2*)(smc + OFF_SG + col * 4);
                        const float2 bt = *(const float2*)(smc + OFF_SBT + col * 4);
                        const float a = acc[m][nt][2 * h + 0];
                        const float b = acc[m][nt][2 * h + 1];
                        float2 o;
                        o.x = ((a - mu) * rstd * gg.x + bt.x) * msk;
                        o.y = ((b - mu) * rstd * gg.y + bt.y) * msk;
                        *(float2*)(op + col) = o;
                    }
                }
        }
        __syncthreads();
    }
}

// ---- launch ----
extern "C" void kernel_launch(void* const* d_in, const int* in_sizes, int n_in,
                              void* d_out, int out_size) {
    const float* nf    = (const float*)d_in[0];
    const float* trans = (const float*)d_in[1];
    const float* sct   = (const float*)d_in[2];
    const float* emask = (const float*)d_in[3];
    const float* flow  = (const float*)d_in[4];
    const float* W_n2e = (const float*)d_in[5];
    const float* b_n2e = (const float*)d_in[6];
    const float* W_rp  = (const float*)d_in[7];
    const float* b_rp  = (const float*)d_in[8];
    const float* W1    = (const float*)d_in[9];
    const float* b1    = (const float*)d_in[10];
    const float* W2    = (const float*)d_in[11];
    const float* b2    = (const float*)d_in[12];
    const float* W3    = (const float*)d_in[13];
    const float* b3    = (const float*)d_in[14];
    const float* lng   = (const float*)d_in[15];
    const float* lnb   = (const float*)d_in[16];
    float* out = (float*)d_out;

    const int N = in_sizes[4];

    k_pre2<<<3 * N - 1 + 64, 128>>>(nf, W_n2e, b_n2e, W1, b1, flow, W_rp, b_rp, W2, W3, N);

    cudaFuncSetAttribute((const void*)k_main,
                         cudaFuncAttributeMaxDynamicSharedMemorySize, SMEM_BYTES);
    k_main<<<304, TW, SMEM_BYTES>>>(trans, sct, emask, W1, b2, b3,
                                    lng, lnb, out, N);
}